// round 12
// baseline (speedup 1.0000x reference)
#include <cuda_runtime.h>
#include <cuda_fp16.h>
#include <cstdint>
#include <math.h>

// Problem constants
#define B   64
#define N   2048
#define D   16
#define H   64
#define DIN 2
#define C   66          // DIN + H
#define KI  132         // 2*C
#define KIP 144         // KI padded to multiple of 16
#define O   64
#define BC  (B*C)       // 4224

// ---------------- scratch ----------------
__device__ int   g_same[2];
__device__ float g_e[3][N][D];
__device__ float g_bias[3][N][O];
__device__ __align__(16) __half g_Af[3][(size_t)N * N];
__device__ __align__(16) __half g_Xh[(size_t)N * BC];
__device__ __align__(16) __half g_Xch[(size_t)N * BC];
__device__ __align__(16) __half g_Yh[3][(size_t)N * BC];
__device__ __align__(16) __half g_Wnh[3][(size_t)N * KI * O];
__device__ float g_r[(size_t)N * B * O];

__device__ __forceinline__ float sigmoidf_(float v) { return 1.0f / (1.0f + expf(-v)); }

__device__ __forceinline__ uint32_t smem_u32(const void* p) {
    uint32_t a;
    asm("{ .reg .u64 t; cvta.to.shared.u64 t, %1; cvt.u32.u64 %0, t; }" : "=r"(a) : "l"(p));
    return a;
}

#define LDM_X4(r, addr) \
    asm volatile("ldmatrix.sync.aligned.m8n8.x4.shared.b16 {%0,%1,%2,%3}, [%4];" \
        : "=r"((r)[0]), "=r"((r)[1]), "=r"((r)[2]), "=r"((r)[3]) : "r"(addr))
#define LDM_X4_T(r, addr) \
    asm volatile("ldmatrix.sync.aligned.m8n8.x4.trans.shared.b16 {%0,%1,%2,%3}, [%4];" \
        : "=r"((r)[0]), "=r"((r)[1]), "=r"((r)[2]), "=r"((r)[3]) : "r"(addr))

#define MMA_F16(d, a, b) \
    asm volatile("mma.sync.aligned.m16n8k16.row.col.f32.f16.f16.f32 " \
        "{%0,%1,%2,%3}, {%4,%5,%6,%7}, {%8,%9}, {%0,%1,%2,%3};" \
        : "+f"((d)[0]), "+f"((d)[1]), "+f"((d)[2]), "+f"((d)[3]) \
        : "r"((a)[0]), "r"((a)[1]), "r"((a)[2]), "r"((a)[3]), "r"((b)[0]), "r"((b)[1]))

#define CP_ASYNC16(smaddr, gptr) \
    asm volatile("cp.async.cg.shared.global [%0], [%1], 16;" :: "r"(smaddr), "l"(gptr) : "memory")
#define CP_COMMIT() asm volatile("cp.async.commit_group;" ::: "memory")
#define CP_WAIT1() asm volatile("cp.async.wait_group 1;" ::: "memory")
#define CP_WAIT0() asm volatile("cp.async.wait_group 0;" ::: "memory")

// ---------------- K1: layernorm embeddings (+ equality flags in block 0) ----------------
__global__ void k_embed(const float* __restrict__ ne, const float* __restrict__ te,
                        const float* __restrict__ gam_z, const float* __restrict__ bet_z,
                        const float* __restrict__ gam_r, const float* __restrict__ bet_r,
                        const float* __restrict__ gam_u, const float* __restrict__ bet_u) {
    int n = blockIdx.x;
    int t = threadIdx.x;
    if (n == 0) {
        bool okr = true, oku = true;
        if (t < D) {
            okr = (gam_r[t] == gam_z[t]) && (bet_r[t] == bet_z[t]);
            oku = (gam_u[t] == gam_z[t]) && (bet_u[t] == bet_z[t]);
        }
        unsigned mr = __ballot_sync(0xffffffffu, okr);
        unsigned mu = __ballot_sync(0xffffffffu, oku);
        if (t == 0) { g_same[0] = (mr == 0xffffffffu); g_same[1] = (mu == 0xffffffffu); }
    }
    float v = 0.f;
    if (t < D) v = ne[n * D + t] + te[t];
    float s = v;
    #pragma unroll
    for (int off = 16; off; off >>= 1) s += __shfl_xor_sync(0xffffffffu, s, off);
    float m = s * (1.0f / D);
    float d2 = (t < D) ? (v - m) * (v - m) : 0.f;
    #pragma unroll
    for (int off = 16; off; off >>= 1) d2 += __shfl_xor_sync(0xffffffffu, d2, off);
    float rs = rsqrtf(d2 * (1.0f / D) + 1e-12f);
    if (t < D) {
        float xn = (v - m) * rs;
        g_e[0][n][t] = xn * gam_z[t] + bet_z[t];
        g_e[1][n][t] = xn * gam_r[t] + bet_r[t];
        g_e[2][n][t] = xn * gam_u[t] + bet_u[t];
    }
}

// ---------------- K2: bias = e @ b_pool ----------------
__global__ void k_bias(const float* __restrict__ bz, const float* __restrict__ br,
                       const float* __restrict__ bu) {
    int idx = blockIdx.x * blockDim.x + threadIdx.x;
    if (idx >= 3 * N * O) return;
    int o = idx % O;
    int n = (idx / O) % N;
    int g = idx / (O * N);
    const float* bp = (g == 0) ? bz : (g == 1) ? br : bu;
    float acc = 0.f;
    #pragma unroll
    for (int d = 0; d < D; d++) acc += g_e[g][n][d] * bp[d * O + o];
    g_bias[g][n][o] = acc;
}

// ---------------- K3: adjacency softmax -> fp16 ----------------
__global__ void __launch_bounds__(256) k_adj() {
    int g = blockIdx.y;
    if (g > 0 && g_same[g - 1]) return;
    int n0 = blockIdx.x * 4;
    int t = threadIdx.x, lane = t & 31, w = t >> 5;
    __shared__ float er[4][16];
    __shared__ float redA[4][8];
    __shared__ float finM[4], finS[4];
    if (t < 64) er[t >> 4][t & 15] = g_e[g][n0 + (t >> 4)][t & 15];
    __syncthreads();

    float dots[4][8];
    float mx[4] = {-1e30f, -1e30f, -1e30f, -1e30f};
    #pragma unroll
    for (int i = 0; i < 8; i++) {
        int col = t + i * 256;
        const float4* em = (const float4*)&g_e[g][col][0];
        float4 e0 = em[0], e1 = em[1], e2 = em[2], e3 = em[3];
        float ec[16] = {e0.x, e0.y, e0.z, e0.w, e1.x, e1.y, e1.z, e1.w,
                        e2.x, e2.y, e2.z, e2.w, e3.x, e3.y, e3.z, e3.w};
        #pragma unroll
        for (int r = 0; r < 4; r++) {
            float d = 0.f;
            #pragma unroll
            for (int k = 0; k < 16; k++) d += er[r][k] * ec[k];
            dots[r][i] = d;
            mx[r] = fmaxf(mx[r], d);
        }
    }
    #pragma unroll
    for (int r = 0; r < 4; r++) {
        float m = mx[r];
        #pragma unroll
        for (int off = 16; off; off >>= 1) m = fmaxf(m, __shfl_xor_sync(0xffffffffu, m, off));
        if (lane == 0) redA[r][w] = m;
    }
    __syncthreads();
    if (t < 4) {
        float M = redA[t][0];
        #pragma unroll
        for (int j = 1; j < 8; j++) M = fmaxf(M, redA[t][j]);
        finM[t] = M;
    }
    __syncthreads();
    #pragma unroll
    for (int r = 0; r < 4; r++) {
        float M = finM[r];
        float s = 0.f;
        #pragma unroll
        for (int i = 0; i < 8; i++) { dots[r][i] = __expf(dots[r][i] - M); s += dots[r][i]; }
        #pragma unroll
        for (int off = 16; off; off >>= 1) s += __shfl_xor_sync(0xffffffffu, s, off);
        if (lane == 0) redA[r][w] = s;
    }
    __syncthreads();
    if (t < 4) {
        float S = 0.f;
        #pragma unroll
        for (int j = 0; j < 8; j++) S += redA[t][j];
        finS[t] = 1.0f / S;
    }
    __syncthreads();
    #pragma unroll
    for (int r = 0; r < 4; r++) {
        float inv = finS[r];
        __half* out = &g_Af[g][(size_t)(n0 + r) * N];
        #pragma unroll
        for (int i = 0; i < 8; i++) out[t + i * 256] = __float2half(dots[r][i] * inv);
    }
}

// ---------------- K4: build Xs fp16 [m][col] ----------------
__global__ void k_buildXh(const float* __restrict__ x, const float* __restrict__ state) {
    int idx = blockIdx.x * blockDim.x + threadIdx.x;
    if (idx >= N * BC) return;
    int m = idx / BC;
    int j = idx - m * BC;
    int b = j / C;
    int c = j - b * C;
    float v = (c < DIN) ? x[(b * N + m) * DIN + c] : state[(b * N + m) * H + (c - DIN)];
    g_Xh[idx] = __float2half(v);
}

// ---------------- K5: Wn = E @ W_pool via MMA ----------------
#define EPAD 24
#define WPADW 136
__global__ void __launch_bounds__(256) k_wn(const float* __restrict__ Wz, const float* __restrict__ Wr,
                                            const float* __restrict__ Wu) {
    int g = blockIdx.z;
    const float* W = (g == 0) ? Wz : (g == 1) ? Wr : Wu;
    int ioBase = blockIdx.x * 128;
    int nBase = blockIdx.y * 64;
    __shared__ __half Eh[64 * EPAD];
    __shared__ __half Wsh[16 * WPADW];
    int t = threadIdx.x, lane = t & 31, wid = t >> 5;

    for (int idx = t; idx < 64 * 16; idx += 256) {
        int r = idx >> 4, d = idx & 15;
        Eh[r * EPAD + d] = __float2half(g_e[g][nBase + r][d]);
    }
    for (int idx = t * 4; idx < 16 * 128; idx += 1024) {
        int d = idx >> 7, c = idx & 127;
        const float4 wv = *(const float4*)&W[(size_t)d * (KI * O) + ioBase + c];
        __half* dst = &Wsh[d * WPADW + c];
        dst[0] = __float2half(wv.x); dst[1] = __float2half(wv.y);
        dst[2] = __float2half(wv.z); dst[3] = __float2half(wv.w);
    }
    __syncthreads();

    int warp_m = wid & 1, warp_n = wid >> 1;
    uint32_t ue = smem_u32(Eh), uw = smem_u32(Wsh);
    uint32_t fa[2][4], fb[2][4];
    #pragma unroll
    for (int mt = 0; mt < 2; mt++) {
        uint32_t a = ue + (uint32_t)(((warp_m * 32 + mt * 16 + (lane & 15)) * EPAD + ((lane >> 4) << 3)) * 2);
        LDM_X4(fa[mt], a);
    }
    #pragma unroll
    for (int p = 0; p < 2; p++) {
        uint32_t bptr = uw + (uint32_t)(((lane & 15) * WPADW + warp_n * 32 + p * 16 + ((lane >> 4) << 3)) * 2);
        LDM_X4_T(fb[p], bptr);
    }
    float acc[2][4][4];
    #pragma unroll
    for (int i = 0; i < 2; i++)
        #pragma unroll
        for (int j = 0; j < 4; j++)
            #pragma unroll
            for (int q = 0; q < 4; q++) acc[i][j][q] = 0.f;
    #pragma unroll
    for (int mt = 0; mt < 2; mt++)
        #pragma unroll
        for (int p = 0; p < 2; p++) {
            MMA_F16(acc[mt][2 * p],     fa[mt], &fb[p][0]);
            MMA_F16(acc[mt][2 * p + 1], fa[mt], &fb[p][2]);
        }

    #pragma unroll
    for (int mt = 0; mt < 2; mt++) {
        int n = nBase + warp_m * 32 + mt * 16 + (lane >> 2);
        #pragma unroll
        for (int nt = 0; nt < 4; nt++) {
            int io = ioBase + warp_n * 32 + nt * 8 + (lane & 3) * 2;
            *(__half2*)&g_Wnh[g][(size_t)n * (KI * O) + io] = __floats2half2_rn(acc[mt][nt][0], acc[mt][nt][1]);
            *(__half2*)&g_Wnh[g][(size_t)(n + 8) * (KI * O) + io] = __floats2half2_rn(acc[mt][nt][2], acc[mt][nt][3]);
        }
    }
}

// ---------------- K6: big GEMM — K-chunk 32, 3-stage cp.async, 3 CTAs/SM, 1 sync/chunk ----------------
#define APAD 40
#define BPAD 136
#define STG_A (128 * APAD)
#define STG_B (32 * BPAD)
#define STG   (STG_A + STG_B)
#define NCH   (N / 32)
#define GEMM_SMEM (3 * STG * 2)

__global__ void __launch_bounds__(256, 3) k_mmagemm(int gate0, int useXc) {
    extern __shared__ __half gsm[];
    int t = threadIdx.x, lane = t & 31, wid = t >> 5;

    const __half* Aptr;
    __half* Yout;
    if (gate0 == 2) {
        Aptr = g_same[1] ? g_Af[0] : g_Af[2];
        Yout = g_Yh[2];
    } else {
        int gate = blockIdx.z;
        if (gate == 1 && g_same[0]) return;
        Aptr = g_Af[gate];
        Yout = g_Yh[gate];
    }
    const __half* Bptr = useXc ? g_Xch : g_Xh;

    int m0 = blockIdx.y * 128, c0 = blockIdx.x * 128;
    int warp_m = wid & 3, warp_n = wid >> 2;

    float acc[2][8][4];
    #pragma unroll
    for (int i = 0; i < 2; i++)
        #pragma unroll
        for (int j = 0; j < 8; j++)
            #pragma unroll
            for (int q = 0; q < 4; q++) acc[i][j][q] = 0.f;

    int arow = t >> 1, aseg = t & 1;
    const __half* gA = Aptr + (size_t)(m0 + arow) * N + aseg * 16;
    uint32_t sAoff = (uint32_t)(arow * APAD + aseg * 16) * 2;
    int brow = t >> 3, bseg = t & 7;
    const __half* gB = Bptr + c0 + bseg * 16;
    uint32_t sBoff = (uint32_t)(brow * BPAD + bseg * 16) * 2;

    uint32_t base = smem_u32(gsm);

    uint32_t aoff[2], boff[4];
    #pragma unroll
    for (int mt = 0; mt < 2; mt++)
        aoff[mt] = (uint32_t)(((warp_m * 32 + mt * 16 + (lane & 15)) * APAD + ((lane >> 4) << 3)) * 2);
    #pragma unroll
    for (int p = 0; p < 4; p++)
        boff[p] = (uint32_t)(((lane & 15) * BPAD + warp_n * 64 + p * 16 + ((lane >> 4) << 3)) * 2);

    #define ISSUE(kc, s) do { \
        const __half* pa = gA + (size_t)(kc) * 32; \
        const __half* pb = gB + (size_t)((kc) * 32 + brow) * BC; \
        uint32_t da = base + (s) * (STG * 2) + sAoff; \
        uint32_t db = base + (s) * (STG * 2) + STG_A * 2 + sBoff; \
        CP_ASYNC16(da, pa); CP_ASYNC16(da + 16, pa + 8); \
        CP_ASYNC16(db, pb); CP_ASYNC16(db + 16, pb + 8); \
        CP_COMMIT(); \
    } while (0)

    ISSUE(0, 0);
    ISSUE(1, 1);

    for (int kc = 0; kc < NCH; kc++) {
        int st = kc % 3;
        if (kc == NCH - 1) { CP_WAIT0(); } else { CP_WAIT1(); }
        __syncthreads();
        // Safe to overwrite stage (kc+2)%3 == (kc-1)%3: the barrier above also
        // separates iteration kc-1's smem reads from this write.
        if (kc + 2 < NCH) ISSUE(kc + 2, (kc + 2) % 3);

        uint32_t ua = base + st * (STG * 2);
        uint32_t ub = ua + STG_A * 2;
        #pragma unroll
        for (int ks = 0; ks < 2; ks++) {
            uint32_t fa[2][4], fb[4][4];
            #pragma unroll
            for (int mt = 0; mt < 2; mt++) LDM_X4(fa[mt], ua + aoff[mt] + ks * 32);
            #pragma unroll
            for (int p = 0; p < 4; p++) LDM_X4_T(fb[p], ub + boff[p] + ks * 16 * BPAD * 2);
            #pragma unroll
            for (int mt = 0; mt < 2; mt++) {
                #pragma unroll
                for (int p = 0; p < 4; p++) {
                    MMA_F16(acc[mt][2 * p],     fa[mt], &fb[p][0]);
                    MMA_F16(acc[mt][2 * p + 1], fa[mt], &fb[p][2]);
                }
            }
        }
    }
    #undef ISSUE

    #pragma unroll
    for (int mt = 0; mt < 2; mt++) {
        int r = m0 + warp_m * 32 + mt * 16 + (lane >> 2);
        #pragma unroll
        for (int nt = 0; nt < 8; nt++) {
            int cc = c0 + warp_n * 64 + nt * 8 + (lane & 3) * 2;
            *(__half2*)&Yout[(size_t)r * BC + cc] = __floats2half2_rn(acc[mt][nt][0], acc[mt][nt][1]);
            *(__half2*)&Yout[(size_t)(r + 8) * BC + cc] = __floats2half2_rn(acc[mt][nt][2], acc[mt][nt][3]);
        }
    }
}

// ---------------- shared helper: per-node gate mini-GEMM via MMA (R8) ----------------
#define XPAD 152
#define WPAD 72

__device__ __forceinline__ void gate_mma(__half* Xall, __half* Wh,
                                         const __half* __restrict__ xsrc,
                                         const __half* __restrict__ ysrc,
                                         const __half* __restrict__ wsrc,
                                         int t, int lane, int wid,
                                         float acc[2][2][4]) {
    for (int cid = t; cid < (KI * O) / 8; cid += 256) {
        int r = cid >> 3, c8 = (cid & 7) * 8;
        *(uint4*)&Wh[r * WPAD + c8] = *(const uint4*)&wsrc[r * O + c8];
    }
    for (int cid = t; cid < 12 * 8; cid += 256) {
        int r = KI + (cid >> 3), c8 = (cid & 7) * 8;
        *(uint4*)&Wh[r * WPAD + c8] = make_uint4(0, 0, 0, 0);
    }
    for (int idx = t; idx < BC; idx += 256) {
        int b = idx / C, c = idx - b * C;
        Xall[b * XPAD + c] = xsrc[idx];
        Xall[b * XPAD + C + c] = ysrc[idx];
    }
    for (int idx = t; idx < 64 * 12; idx += 256) {
        int b = idx / 12, c = KI + idx % 12;
        Xall[b * XPAD + c] = __ushort_as_half((unsigned short)0);
    }
    __syncthreads();

    int warp_m = wid & 1, warp_n = wid >> 1;
    uint32_t ax = smem_u32(Xall), wx = smem_u32(Wh);
    uint32_t aoff[2];
    #pragma unroll
    for (int mt = 0; mt < 2; mt++)
        aoff[mt] = (uint32_t)(((warp_m * 32 + mt * 16 + (lane & 15)) * XPAD + ((lane >> 4) << 3)) * 2);
    uint32_t boff = (uint32_t)(((lane & 15) * WPAD + warp_n * 16 + ((lane >> 4) << 3)) * 2);

    #pragma unroll
    for (int ks = 0; ks < KIP / 16; ks++) {
        uint32_t fa[2][4], fb[4];
        LDM_X4(fa[0], ax + aoff[0] + ks * 32);
        LDM_X4(fa[1], ax + aoff[1] + ks * 32);
        LDM_X4_T(fb, wx + boff + (uint32_t)(ks * 16 * WPAD * 2));
        #pragma unroll
        for (int mt = 0; mt < 2; mt++) {
            MMA_F16(acc[mt][0], fa[mt], &fb[0]);
            MMA_F16(acc[mt][1], fa[mt], &fb[2]);
        }
    }
}

// ---------------- K7: z/r gate apply (R8: grid(N,2)) ----------------
__global__ void __launch_bounds__(256) k_gate_zr(const float* __restrict__ state) {
    __shared__ __half Xall[64 * XPAD];
    __shared__ __half Wh[KIP * WPAD];
    int n = blockIdx.x;
    int g = blockIdx.y;
    int t = threadIdx.x, lane = t & 31, wid = t >> 5;

    const __half* xsrc = g_Xh + (size_t)n * BC;
    const __half* ysrc = ((g == 1) && g_same[0]) ? (g_Yh[0] + (size_t)n * BC)
                                                 : (g_Yh[g] + (size_t)n * BC);
    const __half* wsrc = g_Wnh[g] + (size_t)n * (KI * O);

    float acc[2][2][4];
    #pragma unroll
    for (int i = 0; i < 2; i++)
        #pragma unroll
        for (int j = 0; j < 2; j++)
            #pragma unroll
            for (int q = 0; q < 4; q++) acc[i][j][q] = 0.f;

    gate_mma(Xall, Wh, xsrc, ysrc, wsrc, t, lane, wid, acc);

    int warp_m = wid & 1, warp_n = wid >> 1;
    #pragma unroll
    for (int mt = 0; mt < 2; mt++) {
        int b = warp_m * 32 + mt * 16 + (lane >> 2);
        #pragma unroll
        for (int nt = 0; nt < 2; nt++) {
            int o = warp_n * 16 + nt * 8 + (lane & 3) * 2;
            #pragma unroll
            for (int hf = 0; hf < 2; hf++) {
                int bb = b + hf * 8;
                float2 bi = *(const float2*)&g_bias[g][n][o];
                float s0 = sigmoidf_(acc[mt][nt][2 * hf + 0] + bi.x);
                float s1 = sigmoidf_(acc[mt][nt][2 * hf + 1] + bi.y);
                if (g == 0) {
                    float2 st = *(const float2*)&state[((size_t)bb * N + n) * H + o];
                    *(__half2*)&g_Xch[(size_t)n * BC + bb * C + DIN + o] =
                        __floats2half2_rn(s0 * st.x, s1 * st.y);
                } else {
                    *(float2*)&g_r[((size_t)n * B + bb) * O + o] = make_float2(s0, s1);
                }
            }
        }
    }
    if (g == 0 && t < B * DIN) {
        int b = t >> 1, c = t & 1;
        g_Xch[(size_t)n * BC + b * C + c] = xsrc[b * C + c];
    }
}

// ---------------- K8: final u gate + GRU combine (R8) ----------------
__global__ void __launch_bounds__(256) k_final(const float* __restrict__ state, float* __restrict__ out) {
    __shared__ __half Xall[64 * XPAD];
    __shared__ __half Wh[KIP * WPAD];
    int n = blockIdx.x;
    int t = threadIdx.x, lane = t & 31, wid = t >> 5;

    const __half* xsrc = g_Xch + (size_t)n * BC;
    const __half* ysrc = g_Yh[2] + (size_t)n * BC;
    const __half* wsrc = g_Wnh[2] + (size_t)n * (KI * O);

    float acc[2][2][4];
    #pragma unroll
    for (int i = 0; i < 2; i++)
        #pragma unroll
        for (int j = 0; j < 2; j++)
            #pragma unroll
            for (int q = 0; q < 4; q++) acc[i][j][q] = 0.f;

    gate_mma(Xall, Wh, xsrc, ysrc, wsrc, t, lane, wid, acc);

    int warp_m = wid & 1, warp_n = wid >> 1;
    #pragma unroll
    for (int mt = 0; mt < 2; mt++) {
        int b = warp_m * 32 + mt * 16 + (lane >> 2);
        #pragma unroll
        for (int nt = 0; nt < 2; nt++) {
            int o = warp_n * 16 + nt * 8 + (lane & 3) * 2;
            #pragma unroll
            for (int hf = 0; hf < 2; hf++) {
                int bb = b + hf * 8;
                float2 bi = *(const float2*)&g_bias[2][n][o];
                float hc0 = tanhf(acc[mt][nt][2 * hf + 0] + bi.x);
                float hc1 = tanhf(acc[mt][nt][2 * hf + 1] + bi.y);
                float2 rr = *(const float2*)&g_r[((size_t)n * B + bb) * O + o];
                float2 st = *(const float2*)&state[((size_t)bb * N + n) * H + o];
                *(float2*)&out[((size_t)bb * N + n) * O + o] =
                    make_float2(rr.x * st.x + (1.0f - rr.x) * hc0,
                                rr.y * st.y + (1.0f - rr.y) * hc1);
            }
        }
    }
}

// ---------------- launch ----------------
extern "C" void kernel_launch(void* const* d_in, const int* in_sizes, int n_in,
                              void* d_out, int out_size) {
    const float* x     = (const float*)d_in[0];
    const float* state = (const float*)d_in[1];
    const float* ne    = (const float*)d_in[2];
    const float* te    = (const float*)d_in[3];
    const float* W_z   = (const float*)d_in[4];
    const float* b_z   = (const float*)d_in[5];
    const float* gam_z = (const float*)d_in[6];
    const float* bet_z = (const float*)d_in[7];
    const float* W_r   = (const float*)d_in[8];
    const float* b_r   = (const float*)d_in[9];
    const float* gam_r = (const float*)d_in[10];
    const float* bet_r = (const float*)d_in[11];
    const float* W_u   = (const float*)d_in[12];
    const float* b_u   = (const float*)d_in[13];
    const float* gam_u = (const float*)d_in[14];
    const float* bet_u = (const float*)d_in[15];
    float* out = (float*)d_out;

    cudaFuncSetAttribute(k_mmagemm, cudaFuncAttributeMaxDynamicSharedMemorySize, GEMM_SMEM);

    k_embed<<<N, 32>>>(ne, te, gam_z, bet_z, gam_r, bet_r, gam_u, bet_u);      // #1 (+flags)
    k_adj<<<dim3(N / 4, 3), 256>>>();                                          // #2
    k_buildXh<<<(N * BC + 255) / 256, 256>>>(x, state);                        // #3
    k_mmagemm<<<dim3(BC / 128, N / 128, 2), 256, GEMM_SMEM>>>(0, 0);           // #4 <- profiled
    k_wn<<<dim3(66, 32, 3), 256>>>(W_z, W_r, W_u);                             // #5
    k_bias<<<(3 * N * O + 255) / 256, 256>>>(b_z, b_r, b_u);                   // #6
    k_gate_zr<<<dim3(N, 2), 256>>>(state);                                     // #7
    k_mmagemm<<<dim3(BC / 128, N / 128, 1), 256, GEMM_SMEM>>>(2, 1);           // #8
    k_final<<<N, 256>>>(state, out);                                           // #9
}

// round 14
// speedup vs baseline: 1.2802x; 1.2802x over previous
#include <cuda_runtime.h>
#include <cuda_fp16.h>
#include <cstdint>
#include <math.h>

// Problem constants
#define B   64
#define N   2048
#define D   16
#define H   64
#define DIN 2
#define C   66          // DIN + H
#define KI  132         // 2*C
#define KIP 144         // KI padded to multiple of 16
#define O   64
#define BC  (B*C)       // 4224

// ---------------- scratch ----------------
__device__ int   g_same[2];
__device__ float g_e[3][N][D];
__device__ float g_bias[3][N][O];
__device__ __align__(16) __half g_Af[3][(size_t)N * N];
__device__ __align__(16) __half g_Xh[(size_t)N * BC];
__device__ __align__(16) __half g_Xch[(size_t)N * BC];
__device__ __align__(16) __half g_Yh[3][(size_t)N * BC];
__device__ __align__(16) __half g_Wnh[3][(size_t)N * KI * O];
__device__ float g_r[(size_t)N * B * O];

__device__ __forceinline__ float sigmoidf_(float v) { return 1.0f / (1.0f + expf(-v)); }

__device__ __forceinline__ uint32_t smem_u32(const void* p) {
    uint32_t a;
    asm("{ .reg .u64 t; cvta.to.shared.u64 t, %1; cvt.u32.u64 %0, t; }" : "=r"(a) : "l"(p));
    return a;
}

#define LDM_X4(r, addr) \
    asm volatile("ldmatrix.sync.aligned.m8n8.x4.shared.b16 {%0,%1,%2,%3}, [%4];" \
        : "=r"((r)[0]), "=r"((r)[1]), "=r"((r)[2]), "=r"((r)[3]) : "r"(addr))
#define LDM_X4_T(r, addr) \
    asm volatile("ldmatrix.sync.aligned.m8n8.x4.trans.shared.b16 {%0,%1,%2,%3}, [%4];" \
        : "=r"((r)[0]), "=r"((r)[1]), "=r"((r)[2]), "=r"((r)[3]) : "r"(addr))

#define MMA_F16(d, a, b) \
    asm volatile("mma.sync.aligned.m16n8k16.row.col.f32.f16.f16.f32 " \
        "{%0,%1,%2,%3}, {%4,%5,%6,%7}, {%8,%9}, {%0,%1,%2,%3};" \
        : "+f"((d)[0]), "+f"((d)[1]), "+f"((d)[2]), "+f"((d)[3]) \
        : "r"((a)[0]), "r"((a)[1]), "r"((a)[2]), "r"((a)[3]), "r"((b)[0]), "r"((b)[1]))

#define CP_ASYNC16(smaddr, gptr) \
    asm volatile("cp.async.cg.shared.global [%0], [%1], 16;" :: "r"(smaddr), "l"(gptr) : "memory")
#define CP_COMMIT() asm volatile("cp.async.commit_group;" ::: "memory")
#define CP_WAIT2() asm volatile("cp.async.wait_group 2;" ::: "memory")
#define CP_WAIT0() asm volatile("cp.async.wait_group 0;" ::: "memory")

// ---------------- K1: layernorm embeddings (+ equality flags in block 0) ----------------
__global__ void k_embed(const float* __restrict__ ne, const float* __restrict__ te,
                        const float* __restrict__ gam_z, const float* __restrict__ bet_z,
                        const float* __restrict__ gam_r, const float* __restrict__ bet_r,
                        const float* __restrict__ gam_u, const float* __restrict__ bet_u) {
    int n = blockIdx.x;
    int t = threadIdx.x;
    if (n == 0) {
        bool okr = true, oku = true;
        if (t < D) {
            okr = (gam_r[t] == gam_z[t]) && (bet_r[t] == bet_z[t]);
            oku = (gam_u[t] == gam_z[t]) && (bet_u[t] == bet_z[t]);
        }
        unsigned mr = __ballot_sync(0xffffffffu, okr);
        unsigned mu = __ballot_sync(0xffffffffu, oku);
        if (t == 0) { g_same[0] = (mr == 0xffffffffu); g_same[1] = (mu == 0xffffffffu); }
    }
    float v = 0.f;
    if (t < D) v = ne[n * D + t] + te[t];
    float s = v;
    #pragma unroll
    for (int off = 16; off; off >>= 1) s += __shfl_xor_sync(0xffffffffu, s, off);
    float m = s * (1.0f / D);
    float d2 = (t < D) ? (v - m) * (v - m) : 0.f;
    #pragma unroll
    for (int off = 16; off; off >>= 1) d2 += __shfl_xor_sync(0xffffffffu, d2, off);
    float rs = rsqrtf(d2 * (1.0f / D) + 1e-12f);
    if (t < D) {
        float xn = (v - m) * rs;
        g_e[0][n][t] = xn * gam_z[t] + bet_z[t];
        g_e[1][n][t] = xn * gam_r[t] + bet_r[t];
        g_e[2][n][t] = xn * gam_u[t] + bet_u[t];
    }
}

// ---------------- K2: bias = e @ b_pool ----------------
__global__ void k_bias(const float* __restrict__ bz, const float* __restrict__ br,
                       const float* __restrict__ bu) {
    int idx = blockIdx.x * blockDim.x + threadIdx.x;
    if (idx >= 3 * N * O) return;
    int o = idx % O;
    int n = (idx / O) % N;
    int g = idx / (O * N);
    const float* bp = (g == 0) ? bz : (g == 1) ? br : bu;
    float acc = 0.f;
    #pragma unroll
    for (int d = 0; d < D; d++) acc += g_e[g][n][d] * bp[d * O + o];
    g_bias[g][n][o] = acc;
}

// ---------------- K3: adjacency softmax -> fp16 ----------------
__global__ void __launch_bounds__(256) k_adj() {
    int g = blockIdx.y;
    if (g > 0 && g_same[g - 1]) return;
    int n0 = blockIdx.x * 4;
    int t = threadIdx.x, lane = t & 31, w = t >> 5;
    __shared__ float er[4][16];
    __shared__ float redA[4][8];
    __shared__ float finM[4], finS[4];
    if (t < 64) er[t >> 4][t & 15] = g_e[g][n0 + (t >> 4)][t & 15];
    __syncthreads();

    float dots[4][8];
    float mx[4] = {-1e30f, -1e30f, -1e30f, -1e30f};
    #pragma unroll
    for (int i = 0; i < 8; i++) {
        int col = t + i * 256;
        const float4* em = (const float4*)&g_e[g][col][0];
        float4 e0 = em[0], e1 = em[1], e2 = em[2], e3 = em[3];
        float ec[16] = {e0.x, e0.y, e0.z, e0.w, e1.x, e1.y, e1.z, e1.w,
                        e2.x, e2.y, e2.z, e2.w, e3.x, e3.y, e3.z, e3.w};
        #pragma unroll
        for (int r = 0; r < 4; r++) {
            float d = 0.f;
            #pragma unroll
            for (int k = 0; k < 16; k++) d += er[r][k] * ec[k];
            dots[r][i] = d;
            mx[r] = fmaxf(mx[r], d);
        }
    }
    #pragma unroll
    for (int r = 0; r < 4; r++) {
        float m = mx[r];
        #pragma unroll
        for (int off = 16; off; off >>= 1) m = fmaxf(m, __shfl_xor_sync(0xffffffffu, m, off));
        if (lane == 0) redA[r][w] = m;
    }
    __syncthreads();
    if (t < 4) {
        float M = redA[t][0];
        #pragma unroll
        for (int j = 1; j < 8; j++) M = fmaxf(M, redA[t][j]);
        finM[t] = M;
    }
    __syncthreads();
    #pragma unroll
    for (int r = 0; r < 4; r++) {
        float M = finM[r];
        float s = 0.f;
        #pragma unroll
        for (int i = 0; i < 8; i++) { dots[r][i] = __expf(dots[r][i] - M); s += dots[r][i]; }
        #pragma unroll
        for (int off = 16; off; off >>= 1) s += __shfl_xor_sync(0xffffffffu, s, off);
        if (lane == 0) redA[r][w] = s;
    }
    __syncthreads();
    if (t < 4) {
        float S = 0.f;
        #pragma unroll
        for (int j = 0; j < 8; j++) S += redA[t][j];
        finS[t] = 1.0f / S;
    }
    __syncthreads();
    #pragma unroll
    for (int r = 0; r < 4; r++) {
        float inv = finS[r];
        __half* out = &g_Af[g][(size_t)(n0 + r) * N];
        #pragma unroll
        for (int i = 0; i < 8; i++) out[t + i * 256] = __float2half(dots[r][i] * inv);
    }
}

// ---------------- K4: build Xs fp16 [m][col] ----------------
__global__ void k_buildXh(const float* __restrict__ x, const float* __restrict__ state) {
    int idx = blockIdx.x * blockDim.x + threadIdx.x;
    if (idx >= N * BC) return;
    int m = idx / BC;
    int j = idx - m * BC;
    int b = j / C;
    int c = j - b * C;
    float v = (c < DIN) ? x[(b * N + m) * DIN + c] : state[(b * N + m) * H + (c - DIN)];
    g_Xh[idx] = __float2half(v);
}

// ---------------- K5: Wn = E @ W_pool via MMA ----------------
#define EPAD 24
#define WPADW 136
__global__ void __launch_bounds__(256) k_wn(const float* __restrict__ Wz, const float* __restrict__ Wr,
                                            const float* __restrict__ Wu) {
    int g = blockIdx.z;
    const float* W = (g == 0) ? Wz : (g == 1) ? Wr : Wu;
    int ioBase = blockIdx.x * 128;
    int nBase = blockIdx.y * 64;
    __shared__ __half Eh[64 * EPAD];
    __shared__ __half Wsh[16 * WPADW];
    int t = threadIdx.x, lane = t & 31, wid = t >> 5;

    for (int idx = t; idx < 64 * 16; idx += 256) {
        int r = idx >> 4, d = idx & 15;
        Eh[r * EPAD + d] = __float2half(g_e[g][nBase + r][d]);
    }
    for (int idx = t * 4; idx < 16 * 128; idx += 1024) {
        int d = idx >> 7, c = idx & 127;
        const float4 wv = *(const float4*)&W[(size_t)d * (KI * O) + ioBase + c];
        __half* dst = &Wsh[d * WPADW + c];
        dst[0] = __float2half(wv.x); dst[1] = __float2half(wv.y);
        dst[2] = __float2half(wv.z); dst[3] = __float2half(wv.w);
    }
    __syncthreads();

    int warp_m = wid & 1, warp_n = wid >> 1;
    uint32_t ue = smem_u32(Eh), uw = smem_u32(Wsh);
    uint32_t fa[2][4], fb[2][4];
    #pragma unroll
    for (int mt = 0; mt < 2; mt++) {
        uint32_t a = ue + (uint32_t)(((warp_m * 32 + mt * 16 + (lane & 15)) * EPAD + ((lane >> 4) << 3)) * 2);
        LDM_X4(fa[mt], a);
    }
    #pragma unroll
    for (int p = 0; p < 2; p++) {
        uint32_t bptr = uw + (uint32_t)(((lane & 15) * WPADW + warp_n * 32 + p * 16 + ((lane >> 4) << 3)) * 2);
        LDM_X4_T(fb[p], bptr);
    }
    float acc[2][4][4];
    #pragma unroll
    for (int i = 0; i < 2; i++)
        #pragma unroll
        for (int j = 0; j < 4; j++)
            #pragma unroll
            for (int q = 0; q < 4; q++) acc[i][j][q] = 0.f;
    #pragma unroll
    for (int mt = 0; mt < 2; mt++)
        #pragma unroll
        for (int p = 0; p < 2; p++) {
            MMA_F16(acc[mt][2 * p],     fa[mt], &fb[p][0]);
            MMA_F16(acc[mt][2 * p + 1], fa[mt], &fb[p][2]);
        }

    #pragma unroll
    for (int mt = 0; mt < 2; mt++) {
        int n = nBase + warp_m * 32 + mt * 16 + (lane >> 2);
        #pragma unroll
        for (int nt = 0; nt < 4; nt++) {
            int io = ioBase + warp_n * 32 + nt * 8 + (lane & 3) * 2;
            *(__half2*)&g_Wnh[g][(size_t)n * (KI * O) + io] = __floats2half2_rn(acc[mt][nt][0], acc[mt][nt][1]);
            *(__half2*)&g_Wnh[g][(size_t)(n + 8) * (KI * O) + io] = __floats2half2_rn(acc[mt][nt][2], acc[mt][nt][3]);
        }
    }
}

// ---------------- K6: big GEMM — K-chunk 32, 4-stage cp.async, race-free ordering ----------------
#define APAD 40
#define BPAD 136
#define STG_A (128 * APAD)
#define STG_B (32 * BPAD)
#define STG   (STG_A + STG_B)     // 9472 halves = 18944 B/stage
#define NCH   (N / 32)
#define NSTG  4
#define GEMM_SMEM (NSTG * STG * 2) // 75776 B

__global__ void __launch_bounds__(256) k_mmagemm(int gate0, int useXc) {
    extern __shared__ __half gsm[];
    int t = threadIdx.x, lane = t & 31, wid = t >> 5;

    const __half* Aptr;
    __half* Yout;
    if (gate0 == 2) {
        Aptr = g_same[1] ? g_Af[0] : g_Af[2];
        Yout = g_Yh[2];
    } else {
        int gate = blockIdx.z;
        if (gate == 1 && g_same[0]) return;
        Aptr = g_Af[gate];
        Yout = g_Yh[gate];
    }
    const __half* Bptr = useXc ? g_Xch : g_Xh;

    int m0 = blockIdx.y * 128, c0 = blockIdx.x * 128;
    int warp_m = wid & 3, warp_n = wid >> 2;

    float acc[2][8][4];
    #pragma unroll
    for (int i = 0; i < 2; i++)
        #pragma unroll
        for (int j = 0; j < 8; j++)
            #pragma unroll
            for (int q = 0; q < 4; q++) acc[i][j][q] = 0.f;

    int arow = t >> 1, aseg = t & 1;
    const __half* gA = Aptr + (size_t)(m0 + arow) * N + aseg * 16;
    uint32_t sAoff = (uint32_t)(arow * APAD + aseg * 16) * 2;
    int brow = t >> 3, bseg = t & 7;
    const __half* gB = Bptr + c0 + bseg * 16;
    uint32_t sBoff = (uint32_t)(brow * BPAD + bseg * 16) * 2;

    uint32_t base = smem_u32(gsm);

    uint32_t aoff[2], boff[4];
    #pragma unroll
    for (int mt = 0; mt < 2; mt++)
        aoff[mt] = (uint32_t)(((warp_m * 32 + mt * 16 + (lane & 15)) * APAD + ((lane >> 4) << 3)) * 2);
    #pragma unroll
    for (int p = 0; p < 4; p++)
        boff[p] = (uint32_t)(((lane & 15) * BPAD + warp_n * 64 + p * 16 + ((lane >> 4) << 3)) * 2);

    #define ISSUE(kc, s) do { \
        const __half* pa = gA + (size_t)(kc) * 32; \
        const __half* pb = gB + (size_t)((kc) * 32 + brow) * BC; \
        uint32_t da = base + (s) * (STG * 2) + sAoff; \
        uint32_t db = base + (s) * (STG * 2) + STG_A * 2 + sBoff; \
        CP_ASYNC16(da, pa); CP_ASYNC16(da + 16, pa + 8); \
        CP_ASYNC16(db, pb); CP_ASYNC16(db + 16, pb + 8); \
        CP_COMMIT(); \
    } while (0)

    ISSUE(0, 0);
    ISSUE(1, 1);
    ISSUE(2, 2);

    for (int kc = 0; kc < NCH; kc++) {
        int st = kc & (NSTG - 1);
        // pending groups before wait: {kc, kc+1, kc+2}; wait 2 => group kc landed.
        if (kc >= NCH - 3) { CP_WAIT0(); } else { CP_WAIT2(); }
        __syncthreads();
        // NOW safe to overwrite stage (kc+3)%4 == (kc-1)%4: iteration kc-1's
        // smem reads of that stage completed before the barrier above.
        if (kc + 3 < NCH) ISSUE(kc + 3, (kc + 3) & (NSTG - 1));

        uint32_t ua = base + st * (STG * 2);
        uint32_t ub = ua + STG_A * 2;
        #pragma unroll
        for (int ks = 0; ks < 2; ks++) {
            uint32_t fa[2][4], fb[4][4];
            #pragma unroll
            for (int mt = 0; mt < 2; mt++) LDM_X4(fa[mt], ua + aoff[mt] + ks * 32);
            #pragma unroll
            for (int p = 0; p < 4; p++) LDM_X4_T(fb[p], ub + boff[p] + ks * 16 * BPAD * 2);
            #pragma unroll
            for (int mt = 0; mt < 2; mt++) {
                #pragma unroll
                for (int p = 0; p < 4; p++) {
                    MMA_F16(acc[mt][2 * p],     fa[mt], &fb[p][0]);
                    MMA_F16(acc[mt][2 * p + 1], fa[mt], &fb[p][2]);
                }
            }
        }
    }
    #undef ISSUE

    #pragma unroll
    for (int mt = 0; mt < 2; mt++) {
        int r = m0 + warp_m * 32 + mt * 16 + (lane >> 2);
        #pragma unroll
        for (int nt = 0; nt < 8; nt++) {
            int cc = c0 + warp_n * 64 + nt * 8 + (lane & 3) * 2;
            *(__half2*)&Yout[(size_t)r * BC + cc] = __floats2half2_rn(acc[mt][nt][0], acc[mt][nt][1]);
            *(__half2*)&Yout[(size_t)(r + 8) * BC + cc] = __floats2half2_rn(acc[mt][nt][2], acc[mt][nt][3]);
        }
    }
}

// ---------------- shared helper: per-node gate mini-GEMM via MMA (R8) ----------------
#define XPAD 152
#define WPAD 72

__device__ __forceinline__ void gate_mma(__half* Xall, __half* Wh,
                                         const __half* __restrict__ xsrc,
                                         const __half* __restrict__ ysrc,
                                         const __half* __restrict__ wsrc,
                                         int t, int lane, int wid,
                                         float acc[2][2][4]) {
    for (int cid = t; cid < (KI * O) / 8; cid += 256) {
        int r = cid >> 3, c8 = (cid & 7) * 8;
        *(uint4*)&Wh[r * WPAD + c8] = *(const uint4*)&wsrc[r * O + c8];
    }
    for (int cid = t; cid < 12 * 8; cid += 256) {
        int r = KI + (cid >> 3), c8 = (cid & 7) * 8;
        *(uint4*)&Wh[r * WPAD + c8] = make_uint4(0, 0, 0, 0);
    }
    for (int idx = t; idx < BC; idx += 256) {
        int b = idx / C, c = idx - b * C;
        Xall[b * XPAD + c] = xsrc[idx];
        Xall[b * XPAD + C + c] = ysrc[idx];
    }
    for (int idx = t; idx < 64 * 12; idx += 256) {
        int b = idx / 12, c = KI + idx % 12;
        Xall[b * XPAD + c] = __ushort_as_half((unsigned short)0);
    }
    __syncthreads();

    int warp_m = wid & 1, warp_n = wid >> 1;
    uint32_t ax = smem_u32(Xall), wx = smem_u32(Wh);
    uint32_t aoff[2];
    #pragma unroll
    for (int mt = 0; mt < 2; mt++)
        aoff[mt] = (uint32_t)(((warp_m * 32 + mt * 16 + (lane & 15)) * XPAD + ((lane >> 4) << 3)) * 2);
    uint32_t boff = (uint32_t)(((lane & 15) * WPAD + warp_n * 16 + ((lane >> 4) << 3)) * 2);

    #pragma unroll
    for (int ks = 0; ks < KIP / 16; ks++) {
        uint32_t fa[2][4], fb[4];
        LDM_X4(fa[0], ax + aoff[0] + ks * 32);
        LDM_X4(fa[1], ax + aoff[1] + ks * 32);
        LDM_X4_T(fb, wx + boff + (uint32_t)(ks * 16 * WPAD * 2));
        #pragma unroll
        for (int mt = 0; mt < 2; mt++) {
            MMA_F16(acc[mt][0], fa[mt], &fb[0]);
            MMA_F16(acc[mt][1], fa[mt], &fb[2]);
        }
    }
}

// ---------------- K7: z/r gate apply (R8: grid(N,2)) ----------------
__global__ void __launch_bounds__(256) k_gate_zr(const float* __restrict__ state) {
    __shared__ __half Xall[64 * XPAD];
    __shared__ __half Wh[KIP * WPAD];
    int n = blockIdx.x;
    int g = blockIdx.y;
    int t = threadIdx.x, lane = t & 31, wid = t >> 5;

    const __half* xsrc = g_Xh + (size_t)n * BC;
    const __half* ysrc = ((g == 1) && g_same[0]) ? (g_Yh[0] + (size_t)n * BC)
                                                 : (g_Yh[g] + (size_t)n * BC);
    const __half* wsrc = g_Wnh[g] + (size_t)n * (KI * O);

    float acc[2][2][4];
    #pragma unroll
    for (int i = 0; i < 2; i++)
        #pragma unroll
        for (int j = 0; j < 2; j++)
            #pragma unroll
            for (int q = 0; q < 4; q++) acc[i][j][q] = 0.f;

    gate_mma(Xall, Wh, xsrc, ysrc, wsrc, t, lane, wid, acc);

    int warp_m = wid & 1, warp_n = wid >> 1;
    #pragma unroll
    for (int mt = 0; mt < 2; mt++) {
        int b = warp_m * 32 + mt * 16 + (lane >> 2);
        #pragma unroll
        for (int nt = 0; nt < 2; nt++) {
            int o = warp_n * 16 + nt * 8 + (lane & 3) * 2;
            #pragma unroll
            for (int hf = 0; hf < 2; hf++) {
                int bb = b + hf * 8;
                float2 bi = *(const float2*)&g_bias[g][n][o];
                float s0 = sigmoidf_(acc[mt][nt][2 * hf + 0] + bi.x);
                float s1 = sigmoidf_(acc[mt][nt][2 * hf + 1] + bi.y);
                if (g == 0) {
                    float2 st = *(const float2*)&state[((size_t)bb * N + n) * H + o];
                    *(__half2*)&g_Xch[(size_t)n * BC + bb * C + DIN + o] =
                        __floats2half2_rn(s0 * st.x, s1 * st.y);
                } else {
                    *(float2*)&g_r[((size_t)n * B + bb) * O + o] = make_float2(s0, s1);
                }
            }
        }
    }
    if (g == 0 && t < B * DIN) {
        int b = t >> 1, c = t & 1;
        g_Xch[(size_t)n * BC + b * C + c] = xsrc[b * C + c];
    }
}

// ---------------- K8: final u gate + GRU combine (R8) ----------------
__global__ void __launch_bounds__(256) k_final(const float* __restrict__ state, float* __restrict__ out) {
    __shared__ __half Xall[64 * XPAD];
    __shared__ __half Wh[KIP * WPAD];
    int n = blockIdx.x;
    int t = threadIdx.x, lane = t & 31, wid = t >> 5;

    const __half* xsrc = g_Xch + (size_t)n * BC;
    const __half* ysrc = g_Yh[2] + (size_t)n * BC;
    const __half* wsrc = g_Wnh[2] + (size_t)n * (KI * O);

    float acc[2][2][4];
    #pragma unroll
    for (int i = 0; i < 2; i++)
        #pragma unroll
        for (int j = 0; j < 2; j++)
            #pragma unroll
            for (int q = 0; q < 4; q++) acc[i][j][q] = 0.f;

    gate_mma(Xall, Wh, xsrc, ysrc, wsrc, t, lane, wid, acc);

    int warp_m = wid & 1, warp_n = wid >> 1;
    #pragma unroll
    for (int mt = 0; mt < 2; mt++) {
        int b = warp_m * 32 + mt * 16 + (lane >> 2);
        #pragma unroll
        for (int nt = 0; nt < 2; nt++) {
            int o = warp_n * 16 + nt * 8 + (lane & 3) * 2;
            #pragma unroll
            for (int hf = 0; hf < 2; hf++) {
                int bb = b + hf * 8;
                float2 bi = *(const float2*)&g_bias[2][n][o];
                float hc0 = tanhf(acc[mt][nt][2 * hf + 0] + bi.x);
                float hc1 = tanhf(acc[mt][nt][2 * hf + 1] + bi.y);
                float2 rr = *(const float2*)&g_r[((size_t)n * B + bb) * O + o];
                float2 st = *(const float2*)&state[((size_t)bb * N + n) * H + o];
                *(float2*)&out[((size_t)bb * N + n) * O + o] =
                    make_float2(rr.x * st.x + (1.0f - rr.x) * hc0,
                                rr.y * st.y + (1.0f - rr.y) * hc1);
            }
        }
    }
}

// ---------------- launch ----------------
extern "C" void kernel_launch(void* const* d_in, const int* in_sizes, int n_in,
                              void* d_out, int out_size) {
    const float* x     = (const float*)d_in[0];
    const float* state = (const float*)d_in[1];
    const float* ne    = (const float*)d_in[2];
    const float* te    = (const float*)d_in[3];
    const float* W_z   = (const float*)d_in[4];
    const float* b_z   = (const float*)d_in[5];
    const float* gam_z = (const float*)d_in[6];
    const float* bet_z = (const float*)d_in[7];
    const float* W_r   = (const float*)d_in[8];
    const float* b_r   = (const float*)d_in[9];
    const float* gam_r = (const float*)d_in[10];
    const float* bet_r = (const float*)d_in[11];
    const float* W_u   = (const float*)d_in[12];
    const float* b_u   = (const float*)d_in[13];
    const float* gam_u = (const float*)d_in[14];
    const float* bet_u = (const float*)d_in[15];
    float* out = (float*)d_out;

    cudaFuncSetAttribute(k_mmagemm, cudaFuncAttributeMaxDynamicSharedMemorySize, GEMM_SMEM);

    k_embed<<<N, 32>>>(ne, te, gam_z, bet_z, gam_r, bet_r, gam_u, bet_u);      // #1 (+flags)
    k_adj<<<dim3(N / 4, 3), 256>>>();                                          // #2
    k_buildXh<<<(N * BC + 255) / 256, 256>>>(x, state);                        // #3
    k_mmagemm<<<dim3(BC / 128, N / 128, 2), 256, GEMM_SMEM>>>(0, 0);           // #4 <- profiled
    k_wn<<<dim3(66, 32, 3), 256>>>(W_z, W_r, W_u);                             // #5
    k_bias<<<(3 * N * O + 255) / 256, 256>>>(b_z, b_r, b_u);                   // #6
    k_gate_zr<<<dim3(N, 2), 256>>>(state);                                     // #7
    k_mmagemm<<<dim3(BC / 128, N / 128, 1), 256, GEMM_SMEM>>>(2, 1);           // #8
    k_final<<<N, 256>>>(state, out);                                           // #9
}

// round 16
// speedup vs baseline: 1.3535x; 1.0572x over previous
#include <cuda_runtime.h>
#include <cuda_fp16.h>
#include <cstdint>
#include <math.h>

// Problem constants
#define B   64
#define N   2048
#define D   16
#define H   64
#define DIN 2
#define C   66          // DIN + H
#define KI  132         // 2*C
#define KIP 144         // KI padded to multiple of 16
#define O   64
#define BC  (B*C)       // 4224

// ---------------- scratch ----------------
__device__ int   g_same[2];
__device__ float g_e[3][N][D];
__device__ float g_bias[3][N][O];
__device__ __align__(16) __half g_Af[3][(size_t)N * N];
__device__ __align__(16) __half g_Xh[(size_t)N * BC];
__device__ __align__(16) __half g_Xch[(size_t)N * BC];
__device__ __align__(16) __half g_Yh[3][(size_t)N * BC];
__device__ __align__(16) __half g_Wnh[3][(size_t)N * KI * O];
__device__ float g_r[(size_t)N * B * O];

__device__ __forceinline__ float sigmoidf_(float v) { return 1.0f / (1.0f + expf(-v)); }

__device__ __forceinline__ uint32_t smem_u32(const void* p) {
    uint32_t a;
    asm("{ .reg .u64 t; cvta.to.shared.u64 t, %1; cvt.u32.u64 %0, t; }" : "=r"(a) : "l"(p));
    return a;
}

#define LDM_X4(r, addr) \
    asm volatile("ldmatrix.sync.aligned.m8n8.x4.shared.b16 {%0,%1,%2,%3}, [%4];" \
        : "=r"((r)[0]), "=r"((r)[1]), "=r"((r)[2]), "=r"((r)[3]) : "r"(addr))
#define LDM_X4_T(r, addr) \
    asm volatile("ldmatrix.sync.aligned.m8n8.x4.trans.shared.b16 {%0,%1,%2,%3}, [%4];" \
        : "=r"((r)[0]), "=r"((r)[1]), "=r"((r)[2]), "=r"((r)[3]) : "r"(addr))

#define MMA_F16(d, a, b) \
    asm volatile("mma.sync.aligned.m16n8k16.row.col.f32.f16.f16.f32 " \
        "{%0,%1,%2,%3}, {%4,%5,%6,%7}, {%8,%9}, {%0,%1,%2,%3};" \
        : "+f"((d)[0]), "+f"((d)[1]), "+f"((d)[2]), "+f"((d)[3]) \
        : "r"((a)[0]), "r"((a)[1]), "r"((a)[2]), "r"((a)[3]), "r"((b)[0]), "r"((b)[1]))

#define CP_ASYNC16(smaddr, gptr) \
    asm volatile("cp.async.cg.shared.global [%0], [%1], 16;" :: "r"(smaddr), "l"(gptr) : "memory")
#define CP_COMMIT() asm volatile("cp.async.commit_group;" ::: "memory")
#define CP_WAIT2() asm volatile("cp.async.wait_group 2;" ::: "memory")
#define CP_WAIT0() asm volatile("cp.async.wait_group 0;" ::: "memory")

// ---------------- K1: layernorm embeddings (+ equality flags in block 0) ----------------
__global__ void k_embed(const float* __restrict__ ne, const float* __restrict__ te,
                        const float* __restrict__ gam_z, const float* __restrict__ bet_z,
                        const float* __restrict__ gam_r, const float* __restrict__ bet_r,
                        const float* __restrict__ gam_u, const float* __restrict__ bet_u) {
    int n = blockIdx.x;
    int t = threadIdx.x;
    if (n == 0) {
        bool okr = true, oku = true;
        if (t < D) {
            okr = (gam_r[t] == gam_z[t]) && (bet_r[t] == bet_z[t]);
            oku = (gam_u[t] == gam_z[t]) && (bet_u[t] == bet_z[t]);
        }
        unsigned mr = __ballot_sync(0xffffffffu, okr);
        unsigned mu = __ballot_sync(0xffffffffu, oku);
        if (t == 0) { g_same[0] = (mr == 0xffffffffu); g_same[1] = (mu == 0xffffffffu); }
    }
    float v = 0.f;
    if (t < D) v = ne[n * D + t] + te[t];
    float s = v;
    #pragma unroll
    for (int off = 16; off; off >>= 1) s += __shfl_xor_sync(0xffffffffu, s, off);
    float m = s * (1.0f / D);
    float d2 = (t < D) ? (v - m) * (v - m) : 0.f;
    #pragma unroll
    for (int off = 16; off; off >>= 1) d2 += __shfl_xor_sync(0xffffffffu, d2, off);
    float rs = rsqrtf(d2 * (1.0f / D) + 1e-12f);
    if (t < D) {
        float xn = (v - m) * rs;
        g_e[0][n][t] = xn * gam_z[t] + bet_z[t];
        g_e[1][n][t] = xn * gam_r[t] + bet_r[t];
        g_e[2][n][t] = xn * gam_u[t] + bet_u[t];
    }
}

// ---------------- K2: bias = e @ b_pool ----------------
__global__ void k_bias(const float* __restrict__ bz, const float* __restrict__ br,
                       const float* __restrict__ bu) {
    int idx = blockIdx.x * blockDim.x + threadIdx.x;
    if (idx >= 3 * N * O) return;
    int o = idx % O;
    int n = (idx / O) % N;
    int g = idx / (O * N);
    const float* bp = (g == 0) ? bz : (g == 1) ? br : bu;
    float acc = 0.f;
    #pragma unroll
    for (int d = 0; d < D; d++) acc += g_e[g][n][d] * bp[d * O + o];
    g_bias[g][n][o] = acc;
}

// ---------------- K3: adjacency softmax -> fp16 ----------------
__global__ void __launch_bounds__(256) k_adj() {
    int g = blockIdx.y;
    if (g > 0 && g_same[g - 1]) return;
    int n0 = blockIdx.x * 4;
    int t = threadIdx.x, lane = t & 31, w = t >> 5;
    __shared__ float er[4][16];
    __shared__ float redA[4][8];
    __shared__ float finM[4], finS[4];
    if (t < 64) er[t >> 4][t & 15] = g_e[g][n0 + (t >> 4)][t & 15];
    __syncthreads();

    float dots[4][8];
    float mx[4] = {-1e30f, -1e30f, -1e30f, -1e30f};
    #pragma unroll
    for (int i = 0; i < 8; i++) {
        int col = t + i * 256;
        const float4* em = (const float4*)&g_e[g][col][0];
        float4 e0 = em[0], e1 = em[1], e2 = em[2], e3 = em[3];
        float ec[16] = {e0.x, e0.y, e0.z, e0.w, e1.x, e1.y, e1.z, e1.w,
                        e2.x, e2.y, e2.z, e2.w, e3.x, e3.y, e3.z, e3.w};
        #pragma unroll
        for (int r = 0; r < 4; r++) {
            float d = 0.f;
            #pragma unroll
            for (int k = 0; k < 16; k++) d += er[r][k] * ec[k];
            dots[r][i] = d;
            mx[r] = fmaxf(mx[r], d);
        }
    }
    #pragma unroll
    for (int r = 0; r < 4; r++) {
        float m = mx[r];
        #pragma unroll
        for (int off = 16; off; off >>= 1) m = fmaxf(m, __shfl_xor_sync(0xffffffffu, m, off));
        if (lane == 0) redA[r][w] = m;
    }
    __syncthreads();
    if (t < 4) {
        float M = redA[t][0];
        #pragma unroll
        for (int j = 1; j < 8; j++) M = fmaxf(M, redA[t][j]);
        finM[t] = M;
    }
    __syncthreads();
    #pragma unroll
    for (int r = 0; r < 4; r++) {
        float M = finM[r];
        float s = 0.f;
        #pragma unroll
        for (int i = 0; i < 8; i++) { dots[r][i] = __expf(dots[r][i] - M); s += dots[r][i]; }
        #pragma unroll
        for (int off = 16; off; off >>= 1) s += __shfl_xor_sync(0xffffffffu, s, off);
        if (lane == 0) redA[r][w] = s;
    }
    __syncthreads();
    if (t < 4) {
        float S = 0.f;
        #pragma unroll
        for (int j = 0; j < 8; j++) S += redA[t][j];
        finS[t] = 1.0f / S;
    }
    __syncthreads();
    #pragma unroll
    for (int r = 0; r < 4; r++) {
        float inv = finS[r];
        __half* out = &g_Af[g][(size_t)(n0 + r) * N];
        #pragma unroll
        for (int i = 0; i < 8; i++) out[t + i * 256] = __float2half(dots[r][i] * inv);
    }
}

// ---------------- K4: build Xs fp16 [m][col] ----------------
__global__ void k_buildXh(const float* __restrict__ x, const float* __restrict__ state) {
    int idx = blockIdx.x * blockDim.x + threadIdx.x;
    if (idx >= N * BC) return;
    int m = idx / BC;
    int j = idx - m * BC;
    int b = j / C;
    int c = j - b * C;
    float v = (c < DIN) ? x[(b * N + m) * DIN + c] : state[(b * N + m) * H + (c - DIN)];
    g_Xh[idx] = __float2half(v);
}

// ---------------- K5: Wn = E @ W_pool via MMA ----------------
#define EPAD 24
#define WPADW 136
__global__ void __launch_bounds__(256) k_wn(const float* __restrict__ Wz, const float* __restrict__ Wr,
                                            const float* __restrict__ Wu) {
    int g = blockIdx.z;
    const float* W = (g == 0) ? Wz : (g == 1) ? Wr : Wu;
    int ioBase = blockIdx.x * 128;
    int nBase = blockIdx.y * 64;
    __shared__ __half Eh[64 * EPAD];
    __shared__ __half Wsh[16 * WPADW];
    int t = threadIdx.x, lane = t & 31, wid = t >> 5;

    for (int idx = t; idx < 64 * 16; idx += 256) {
        int r = idx >> 4, d = idx & 15;
        Eh[r * EPAD + d] = __float2half(g_e[g][nBase + r][d]);
    }
    for (int idx = t * 4; idx < 16 * 128; idx += 1024) {
        int d = idx >> 7, c = idx & 127;
        const float4 wv = *(const float4*)&W[(size_t)d * (KI * O) + ioBase + c];
        __half* dst = &Wsh[d * WPADW + c];
        dst[0] = __float2half(wv.x); dst[1] = __float2half(wv.y);
        dst[2] = __float2half(wv.z); dst[3] = __float2half(wv.w);
    }
    __syncthreads();

    int warp_m = wid & 1, warp_n = wid >> 1;
    uint32_t ue = smem_u32(Eh), uw = smem_u32(Wsh);
    uint32_t fa[2][4], fb[2][4];
    #pragma unroll
    for (int mt = 0; mt < 2; mt++) {
        uint32_t a = ue + (uint32_t)(((warp_m * 32 + mt * 16 + (lane & 15)) * EPAD + ((lane >> 4) << 3)) * 2);
        LDM_X4(fa[mt], a);
    }
    #pragma unroll
    for (int p = 0; p < 2; p++) {
        uint32_t bptr = uw + (uint32_t)(((lane & 15) * WPADW + warp_n * 32 + p * 16 + ((lane >> 4) << 3)) * 2);
        LDM_X4_T(fb[p], bptr);
    }
    float acc[2][4][4];
    #pragma unroll
    for (int i = 0; i < 2; i++)
        #pragma unroll
        for (int j = 0; j < 4; j++)
            #pragma unroll
            for (int q = 0; q < 4; q++) acc[i][j][q] = 0.f;
    #pragma unroll
    for (int mt = 0; mt < 2; mt++)
        #pragma unroll
        for (int p = 0; p < 2; p++) {
            MMA_F16(acc[mt][2 * p],     fa[mt], &fb[p][0]);
            MMA_F16(acc[mt][2 * p + 1], fa[mt], &fb[p][2]);
        }

    #pragma unroll
    for (int mt = 0; mt < 2; mt++) {
        int n = nBase + warp_m * 32 + mt * 16 + (lane >> 2);
        #pragma unroll
        for (int nt = 0; nt < 4; nt++) {
            int io = ioBase + warp_n * 32 + nt * 8 + (lane & 3) * 2;
            *(__half2*)&g_Wnh[g][(size_t)n * (KI * O) + io] = __floats2half2_rn(acc[mt][nt][0], acc[mt][nt][1]);
            *(__half2*)&g_Wnh[g][(size_t)(n + 8) * (KI * O) + io] = __floats2half2_rn(acc[mt][nt][2], acc[mt][nt][3]);
        }
    }
}

// ---------------- K6: big GEMM — K-chunk 32, 4-stage cp.async, race-free ordering ----------------
#define APAD 40
#define BPAD 136
#define STG_A (128 * APAD)
#define STG_B (32 * BPAD)
#define STG   (STG_A + STG_B)     // 9472 halves = 18944 B/stage
#define NCH   (N / 32)
#define NSTG  4
#define GEMM_SMEM (NSTG * STG * 2) // 75776 B

__global__ void __launch_bounds__(256) k_mmagemm(int gate0, int useXc) {
    extern __shared__ __half gsm[];
    int t = threadIdx.x, lane = t & 31, wid = t >> 5;

    const __half* Aptr;
    __half* Yout;
    if (gate0 == 2) {
        Aptr = g_same[1] ? g_Af[0] : g_Af[2];
        Yout = g_Yh[2];
    } else {
        int gate = blockIdx.z;
        if (gate == 1 && g_same[0]) return;
        Aptr = g_Af[gate];
        Yout = g_Yh[gate];
    }
    const __half* Bptr = useXc ? g_Xch : g_Xh;

    int m0 = blockIdx.y * 128, c0 = blockIdx.x * 128;
    int warp_m = wid & 3, warp_n = wid >> 2;

    float acc[2][8][4];
    #pragma unroll
    for (int i = 0; i < 2; i++)
        #pragma unroll
        for (int j = 0; j < 8; j++)
            #pragma unroll
            for (int q = 0; q < 4; q++) acc[i][j][q] = 0.f;

    int arow = t >> 1, aseg = t & 1;
    const __half* gA = Aptr + (size_t)(m0 + arow) * N + aseg * 16;
    uint32_t sAoff = (uint32_t)(arow * APAD + aseg * 16) * 2;
    int brow = t >> 3, bseg = t & 7;
    const __half* gB = Bptr + c0 + bseg * 16;
    uint32_t sBoff = (uint32_t)(brow * BPAD + bseg * 16) * 2;

    uint32_t base = smem_u32(gsm);

    uint32_t aoff[2], boff[4];
    #pragma unroll
    for (int mt = 0; mt < 2; mt++)
        aoff[mt] = (uint32_t)(((warp_m * 32 + mt * 16 + (lane & 15)) * APAD + ((lane >> 4) << 3)) * 2);
    #pragma unroll
    for (int p = 0; p < 4; p++)
        boff[p] = (uint32_t)(((lane & 15) * BPAD + warp_n * 64 + p * 16 + ((lane >> 4) << 3)) * 2);

    #define ISSUE(kc, s) do { \
        const __half* pa = gA + (size_t)(kc) * 32; \
        const __half* pb = gB + (size_t)((kc) * 32 + brow) * BC; \
        uint32_t da = base + (s) * (STG * 2) + sAoff; \
        uint32_t db = base + (s) * (STG * 2) + STG_A * 2 + sBoff; \
        CP_ASYNC16(da, pa); CP_ASYNC16(da + 16, pa + 8); \
        CP_ASYNC16(db, pb); CP_ASYNC16(db + 16, pb + 8); \
        CP_COMMIT(); \
    } while (0)

    ISSUE(0, 0);
    ISSUE(1, 1);
    ISSUE(2, 2);

    for (int kc = 0; kc < NCH; kc++) {
        int st = kc & (NSTG - 1);
        // pending groups before wait: {kc, kc+1, kc+2}; wait 2 => group kc landed.
        if (kc >= NCH - 3) { CP_WAIT0(); } else { CP_WAIT2(); }
        __syncthreads();
        // NOW safe to overwrite stage (kc+3)%4 == (kc-1)%4: iteration kc-1's
        // smem reads of that stage completed before the barrier above.
        if (kc + 3 < NCH) ISSUE(kc + 3, (kc + 3) & (NSTG - 1));

        uint32_t ua = base + st * (STG * 2);
        uint32_t ub = ua + STG_A * 2;
        #pragma unroll
        for (int ks = 0; ks < 2; ks++) {
            uint32_t fa[2][4], fb[4][4];
            #pragma unroll
            for (int mt = 0; mt < 2; mt++) LDM_X4(fa[mt], ua + aoff[mt] + ks * 32);
            #pragma unroll
            for (int p = 0; p < 4; p++) LDM_X4_T(fb[p], ub + boff[p] + ks * 16 * BPAD * 2);
            #pragma unroll
            for (int mt = 0; mt < 2; mt++) {
                #pragma unroll
                for (int p = 0; p < 4; p++) {
                    MMA_F16(acc[mt][2 * p],     fa[mt], &fb[p][0]);
                    MMA_F16(acc[mt][2 * p + 1], fa[mt], &fb[p][2]);
                }
            }
        }
    }
    #undef ISSUE

    #pragma unroll
    for (int mt = 0; mt < 2; mt++) {
        int r = m0 + warp_m * 32 + mt * 16 + (lane >> 2);
        #pragma unroll
        for (int nt = 0; nt < 8; nt++) {
            int cc = c0 + warp_n * 64 + nt * 8 + (lane & 3) * 2;
            *(__half2*)&Yout[(size_t)r * BC + cc] = __floats2half2_rn(acc[mt][nt][0], acc[mt][nt][1]);
            *(__half2*)&Yout[(size_t)(r + 8) * BC + cc] = __floats2half2_rn(acc[mt][nt][2], acc[mt][nt][3]);
        }
    }
}

// ---------------- shared helper: per-node gate mini-GEMM via MMA (R8) ----------------
#define XPAD 152
#define WPAD 72

__device__ __forceinline__ void gate_mma(__half* Xall, __half* Wh,
                                         const __half* __restrict__ xsrc,
                                         const __half* __restrict__ ysrc,
                                         const __half* __restrict__ wsrc,
                                         int t, int lane, int wid,
                                         float acc[2][2][4]) {
    for (int cid = t; cid < (KI * O) / 8; cid += 256) {
        int r = cid >> 3, c8 = (cid & 7) * 8;
        *(uint4*)&Wh[r * WPAD + c8] = *(const uint4*)&wsrc[r * O + c8];
    }
    for (int cid = t; cid < 12 * 8; cid += 256) {
        int r = KI + (cid >> 3), c8 = (cid & 7) * 8;
        *(uint4*)&Wh[r * WPAD + c8] = make_uint4(0, 0, 0, 0);
    }
    for (int idx = t; idx < BC; idx += 256) {
        int b = idx / C, c = idx - b * C;
        Xall[b * XPAD + c] = xsrc[idx];
        Xall[b * XPAD + C + c] = ysrc[idx];
    }
    for (int idx = t; idx < 64 * 12; idx += 256) {
        int b = idx / 12, c = KI + idx % 12;
        Xall[b * XPAD + c] = __ushort_as_half((unsigned short)0);
    }
    __syncthreads();

    int warp_m = wid & 1, warp_n = wid >> 1;
    uint32_t ax = smem_u32(Xall), wx = smem_u32(Wh);
    uint32_t aoff[2];
    #pragma unroll
    for (int mt = 0; mt < 2; mt++)
        aoff[mt] = (uint32_t)(((warp_m * 32 + mt * 16 + (lane & 15)) * XPAD + ((lane >> 4) << 3)) * 2);
    uint32_t boff = (uint32_t)(((lane & 15) * WPAD + warp_n * 16 + ((lane >> 4) << 3)) * 2);

    #pragma unroll
    for (int ks = 0; ks < KIP / 16; ks++) {
        uint32_t fa[2][4], fb[4];
        LDM_X4(fa[0], ax + aoff[0] + ks * 32);
        LDM_X4(fa[1], ax + aoff[1] + ks * 32);
        LDM_X4_T(fb, wx + boff + (uint32_t)(ks * 16 * WPAD * 2));
        #pragma unroll
        for (int mt = 0; mt < 2; mt++) {
            MMA_F16(acc[mt][0], fa[mt], &fb[0]);
            MMA_F16(acc[mt][1], fa[mt], &fb[2]);
        }
    }
}

// ---------------- K7: z/r gate apply (R8: grid(N,2)) ----------------
__global__ void __launch_bounds__(256) k_gate_zr(const float* __restrict__ state) {
    __shared__ __half Xall[64 * XPAD];
    __shared__ __half Wh[KIP * WPAD];
    int n = blockIdx.x;
    int g = blockIdx.y;
    int t = threadIdx.x, lane = t & 31, wid = t >> 5;

    const __half* xsrc = g_Xh + (size_t)n * BC;
    const __half* ysrc = ((g == 1) && g_same[0]) ? (g_Yh[0] + (size_t)n * BC)
                                                 : (g_Yh[g] + (size_t)n * BC);
    const __half* wsrc = g_Wnh[g] + (size_t)n * (KI * O);

    float acc[2][2][4];
    #pragma unroll
    for (int i = 0; i < 2; i++)
        #pragma unroll
        for (int j = 0; j < 2; j++)
            #pragma unroll
            for (int q = 0; q < 4; q++) acc[i][j][q] = 0.f;

    gate_mma(Xall, Wh, xsrc, ysrc, wsrc, t, lane, wid, acc);

    int warp_m = wid & 1, warp_n = wid >> 1;
    #pragma unroll
    for (int mt = 0; mt < 2; mt++) {
        int b = warp_m * 32 + mt * 16 + (lane >> 2);
        #pragma unroll
        for (int nt = 0; nt < 2; nt++) {
            int o = warp_n * 16 + nt * 8 + (lane & 3) * 2;
            #pragma unroll
            for (int hf = 0; hf < 2; hf++) {
                int bb = b + hf * 8;
                float2 bi = *(const float2*)&g_bias[g][n][o];
                float s0 = sigmoidf_(acc[mt][nt][2 * hf + 0] + bi.x);
                float s1 = sigmoidf_(acc[mt][nt][2 * hf + 1] + bi.y);
                if (g == 0) {
                    float2 st = *(const float2*)&state[((size_t)bb * N + n) * H + o];
                    *(__half2*)&g_Xch[(size_t)n * BC + bb * C + DIN + o] =
                        __floats2half2_rn(s0 * st.x, s1 * st.y);
                } else {
                    *(float2*)&g_r[((size_t)n * B + bb) * O + o] = make_float2(s0, s1);
                }
            }
        }
    }
    if (g == 0 && t < B * DIN) {
        int b = t >> 1, c = t & 1;
        g_Xch[(size_t)n * BC + b * C + c] = xsrc[b * C + c];
    }
}

// ---------------- K8: final u gate + GRU combine (R8) ----------------
__global__ void __launch_bounds__(256) k_final(const float* __restrict__ state, float* __restrict__ out) {
    __shared__ __half Xall[64 * XPAD];
    __shared__ __half Wh[KIP * WPAD];
    int n = blockIdx.x;
    int t = threadIdx.x, lane = t & 31, wid = t >> 5;

    const __half* xsrc = g_Xch + (size_t)n * BC;
    const __half* ysrc = g_Yh[2] + (size_t)n * BC;
    const __half* wsrc = g_Wnh[2] + (size_t)n * (KI * O);

    float acc[2][2][4];
    #pragma unroll
    for (int i = 0; i < 2; i++)
        #pragma unroll
        for (int j = 0; j < 2; j++)
            #pragma unroll
            for (int q = 0; q < 4; q++) acc[i][j][q] = 0.f;

    gate_mma(Xall, Wh, xsrc, ysrc, wsrc, t, lane, wid, acc);

    int warp_m = wid & 1, warp_n = wid >> 1;
    #pragma unroll
    for (int mt = 0; mt < 2; mt++) {
        int b = warp_m * 32 + mt * 16 + (lane >> 2);
        #pragma unroll
        for (int nt = 0; nt < 2; nt++) {
            int o = warp_n * 16 + nt * 8 + (lane & 3) * 2;
            #pragma unroll
            for (int hf = 0; hf < 2; hf++) {
                int bb = b + hf * 8;
                float2 bi = *(const float2*)&g_bias[2][n][o];
                float hc0 = tanhf(acc[mt][nt][2 * hf + 0] + bi.x);
                float hc1 = tanhf(acc[mt][nt][2 * hf + 1] + bi.y);
                float2 rr = *(const float2*)&g_r[((size_t)n * B + bb) * O + o];
                float2 st = *(const float2*)&state[((size_t)bb * N + n) * H + o];
                *(float2*)&out[((size_t)bb * N + n) * O + o] =
                    make_float2(rr.x * st.x + (1.0f - rr.x) * hc0,
                                rr.y * st.y + (1.0f - rr.y) * hc1);
            }
        }
    }
}

// ---------------- launch (two streams, event-linked, graph-capturable) ----------------
extern "C" void kernel_launch(void* const* d_in, const int* in_sizes, int n_in,
                              void* d_out, int out_size) {
    const float* x     = (const float*)d_in[0];
    const float* state = (const float*)d_in[1];
    const float* ne    = (const float*)d_in[2];
    const float* te    = (const float*)d_in[3];
    const float* W_z   = (const float*)d_in[4];
    const float* b_z   = (const float*)d_in[5];
    const float* gam_z = (const float*)d_in[6];
    const float* bet_z = (const float*)d_in[7];
    const float* W_r   = (const float*)d_in[8];
    const float* b_r   = (const float*)d_in[9];
    const float* gam_r = (const float*)d_in[10];
    const float* bet_r = (const float*)d_in[11];
    const float* W_u   = (const float*)d_in[12];
    const float* b_u   = (const float*)d_in[13];
    const float* gam_u = (const float*)d_in[14];
    const float* bet_u = (const float*)d_in[15];
    float* out = (float*)d_out;

    static cudaStream_t s2 = nullptr;
    static cudaEvent_t eEmb = nullptr, eBXh = nullptr, eW = nullptr;
    if (s2 == nullptr) {
        cudaStreamCreateWithFlags(&s2, cudaStreamNonBlocking);
        cudaEventCreateWithFlags(&eEmb, cudaEventDisableTiming);
        cudaEventCreateWithFlags(&eBXh, cudaEventDisableTiming);
        cudaEventCreateWithFlags(&eW, cudaEventDisableTiming);
        cudaFuncSetAttribute(k_mmagemm, cudaFuncAttributeMaxDynamicSharedMemorySize, GEMM_SMEM);
    }

    // main stream (0): embed -> adj -> GEMM_z -> gate_zr -> GEMM_u -> final
    // side stream s2: buildXh -> wn -> bias (forked after embed, joined before gate_zr)
    k_embed<<<N, 32>>>(ne, te, gam_z, bet_z, gam_r, bet_r, gam_u, bet_u);       // #1
    cudaEventRecord(eEmb, 0);
    cudaStreamWaitEvent(s2, eEmb, 0);

    k_adj<<<dim3(N / 4, 3), 256>>>();                                           // #2 (stream 0)
    k_buildXh<<<(N * BC + 255) / 256, 256, 0, s2>>>(x, state);                  // #3 (s2)
    cudaEventRecord(eBXh, s2);

    cudaStreamWaitEvent(0, eBXh, 0);
    k_mmagemm<<<dim3(BC / 128, N / 128, 2), 256, GEMM_SMEM>>>(0, 0);            // #4 <- profiled

    k_wn<<<dim3(66, 32, 3), 256, 0, s2>>>(W_z, W_r, W_u);                       // #5 (s2)
    k_bias<<<(3 * N * O + 255) / 256, 256, 0, s2>>>(b_z, b_r, b_u);             // #6 (s2)
    cudaEventRecord(eW, s2);

    cudaStreamWaitEvent(0, eW, 0);
    k_gate_zr<<<dim3(N, 2), 256>>>(state);                                      // #7
    k_mmagemm<<<dim3(BC / 128, N / 128, 1), 256, GEMM_SMEM>>>(2, 1);            // #8
    k_final<<<N, 256>>>(state, out);                                            // #9
}

// round 17
// speedup vs baseline: 1.3950x; 1.0307x over previous
#include <cuda_runtime.h>
#include <cuda_fp16.h>
#include <cstdint>
#include <math.h>

// Problem constants
#define B   64
#define N   2048
#define D   16
#define H   64
#define DIN 2
#define C   66          // DIN + H
#define KI  132         // 2*C
#define KIP 144         // KI padded to multiple of 16
#define O   64
#define BC  (B*C)       // 4224

// ---------------- scratch ----------------
__device__ int   g_same[2];
__device__ float g_e[3][N][D];
__device__ float g_bias[3][N][O];
__device__ __align__(16) __half g_Af[3][(size_t)N * N];
__device__ __align__(16) __half g_Xh[(size_t)N * BC];
__device__ __align__(16) __half g_Xch[(size_t)N * BC];
__device__ __align__(16) __half g_Yh[3][(size_t)N * BC];
__device__ __align__(16) __half g_Wnh[3][(size_t)N * KI * O];
__device__ float g_r[(size_t)N * B * O];

__device__ __forceinline__ float sigmoidf_(float v) { return 1.0f / (1.0f + expf(-v)); }

__device__ __forceinline__ uint32_t smem_u32(const void* p) {
    uint32_t a;
    asm("{ .reg .u64 t; cvta.to.shared.u64 t, %1; cvt.u32.u64 %0, t; }" : "=r"(a) : "l"(p));
    return a;
}

#define LDM_X4(r, addr) \
    asm volatile("ldmatrix.sync.aligned.m8n8.x4.shared.b16 {%0,%1,%2,%3}, [%4];" \
        : "=r"((r)[0]), "=r"((r)[1]), "=r"((r)[2]), "=r"((r)[3]) : "r"(addr))
#define LDM_X4_T(r, addr) \
    asm volatile("ldmatrix.sync.aligned.m8n8.x4.trans.shared.b16 {%0,%1,%2,%3}, [%4];" \
        : "=r"((r)[0]), "=r"((r)[1]), "=r"((r)[2]), "=r"((r)[3]) : "r"(addr))

#define MMA_F16(d, a, b) \
    asm volatile("mma.sync.aligned.m16n8k16.row.col.f32.f16.f16.f32 " \
        "{%0,%1,%2,%3}, {%4,%5,%6,%7}, {%8,%9}, {%0,%1,%2,%3};" \
        : "+f"((d)[0]), "+f"((d)[1]), "+f"((d)[2]), "+f"((d)[3]) \
        : "r"((a)[0]), "r"((a)[1]), "r"((a)[2]), "r"((a)[3]), "r"((b)[0]), "r"((b)[1]))

#define CP_ASYNC16(smaddr, gptr) \
    asm volatile("cp.async.cg.shared.global [%0], [%1], 16;" :: "r"(smaddr), "l"(gptr) : "memory")
#define CP_COMMIT() asm volatile("cp.async.commit_group;" ::: "memory")
#define CP_WAIT2() asm volatile("cp.async.wait_group 2;" ::: "memory")
#define CP_WAIT0() asm volatile("cp.async.wait_group 0;" ::: "memory")

// ---------------- K1: layernorm embeddings (+ equality flags in block 0) ----------------
__global__ void k_embed(const float* __restrict__ ne, const float* __restrict__ te,
                        const float* __restrict__ gam_z, const float* __restrict__ bet_z,
                        const float* __restrict__ gam_r, const float* __restrict__ bet_r,
                        const float* __restrict__ gam_u, const float* __restrict__ bet_u) {
    int n = blockIdx.x;
    int t = threadIdx.x;
    if (n == 0) {
        bool okr = true, oku = true;
        if (t < D) {
            okr = (gam_r[t] == gam_z[t]) && (bet_r[t] == bet_z[t]);
            oku = (gam_u[t] == gam_z[t]) && (bet_u[t] == bet_z[t]);
        }
        unsigned mr = __ballot_sync(0xffffffffu, okr);
        unsigned mu = __ballot_sync(0xffffffffu, oku);
        if (t == 0) { g_same[0] = (mr == 0xffffffffu); g_same[1] = (mu == 0xffffffffu); }
    }
    float v = 0.f;
    if (t < D) v = ne[n * D + t] + te[t];
    float s = v;
    #pragma unroll
    for (int off = 16; off; off >>= 1) s += __shfl_xor_sync(0xffffffffu, s, off);
    float m = s * (1.0f / D);
    float d2 = (t < D) ? (v - m) * (v - m) : 0.f;
    #pragma unroll
    for (int off = 16; off; off >>= 1) d2 += __shfl_xor_sync(0xffffffffu, d2, off);
    float rs = rsqrtf(d2 * (1.0f / D) + 1e-12f);
    if (t < D) {
        float xn = (v - m) * rs;
        g_e[0][n][t] = xn * gam_z[t] + bet_z[t];
        g_e[1][n][t] = xn * gam_r[t] + bet_r[t];
        g_e[2][n][t] = xn * gam_u[t] + bet_u[t];
    }
}

// ---------------- K2: bias = e @ b_pool ----------------
__global__ void k_bias(const float* __restrict__ bz, const float* __restrict__ br,
                       const float* __restrict__ bu) {
    int idx = blockIdx.x * blockDim.x + threadIdx.x;
    if (idx >= 3 * N * O) return;
    int o = idx % O;
    int n = (idx / O) % N;
    int g = idx / (O * N);
    const float* bp = (g == 0) ? bz : (g == 1) ? br : bu;
    float acc = 0.f;
    #pragma unroll
    for (int d = 0; d < D; d++) acc += g_e[g][n][d] * bp[d * O + o];
    g_bias[g][n][o] = acc;
}

// ---------------- K3: adjacency softmax -> fp16 ----------------
__global__ void __launch_bounds__(256) k_adj() {
    int g = blockIdx.y;
    if (g > 0 && g_same[g - 1]) return;
    int n0 = blockIdx.x * 4;
    int t = threadIdx.x, lane = t & 31, w = t >> 5;
    __shared__ float er[4][16];
    __shared__ float redA[4][8];
    __shared__ float finM[4], finS[4];
    if (t < 64) er[t >> 4][t & 15] = g_e[g][n0 + (t >> 4)][t & 15];
    __syncthreads();

    float dots[4][8];
    float mx[4] = {-1e30f, -1e30f, -1e30f, -1e30f};
    #pragma unroll
    for (int i = 0; i < 8; i++) {
        int col = t + i * 256;
        const float4* em = (const float4*)&g_e[g][col][0];
        float4 e0 = em[0], e1 = em[1], e2 = em[2], e3 = em[3];
        float ec[16] = {e0.x, e0.y, e0.z, e0.w, e1.x, e1.y, e1.z, e1.w,
                        e2.x, e2.y, e2.z, e2.w, e3.x, e3.y, e3.z, e3.w};
        #pragma unroll
        for (int r = 0; r < 4; r++) {
            float d = 0.f;
            #pragma unroll
            for (int k = 0; k < 16; k++) d += er[r][k] * ec[k];
            dots[r][i] = d;
            mx[r] = fmaxf(mx[r], d);
        }
    }
    #pragma unroll
    for (int r = 0; r < 4; r++) {
        float m = mx[r];
        #pragma unroll
        for (int off = 16; off; off >>= 1) m = fmaxf(m, __shfl_xor_sync(0xffffffffu, m, off));
        if (lane == 0) redA[r][w] = m;
    }
    __syncthreads();
    if (t < 4) {
        float M = redA[t][0];
        #pragma unroll
        for (int j = 1; j < 8; j++) M = fmaxf(M, redA[t][j]);
        finM[t] = M;
    }
    __syncthreads();
    #pragma unroll
    for (int r = 0; r < 4; r++) {
        float M = finM[r];
        float s = 0.f;
        #pragma unroll
        for (int i = 0; i < 8; i++) { dots[r][i] = __expf(dots[r][i] - M); s += dots[r][i]; }
        #pragma unroll
        for (int off = 16; off; off >>= 1) s += __shfl_xor_sync(0xffffffffu, s, off);
        if (lane == 0) redA[r][w] = s;
    }
    __syncthreads();
    if (t < 4) {
        float S = 0.f;
        #pragma unroll
        for (int j = 0; j < 8; j++) S += redA[t][j];
        finS[t] = 1.0f / S;
    }
    __syncthreads();
    #pragma unroll
    for (int r = 0; r < 4; r++) {
        float inv = finS[r];
        __half* out = &g_Af[g][(size_t)(n0 + r) * N];
        #pragma unroll
        for (int i = 0; i < 8; i++) out[t + i * 256] = __float2half(dots[r][i] * inv);
    }
}

// ---------------- K4: build Xs fp16 [m][col] ----------------
__global__ void k_buildXh(const float* __restrict__ x, const float* __restrict__ state) {
    int idx = blockIdx.x * blockDim.x + threadIdx.x;
    if (idx >= N * BC) return;
    int m = idx / BC;
    int j = idx - m * BC;
    int b = j / C;
    int c = j - b * C;
    float v = (c < DIN) ? x[(b * N + m) * DIN + c] : state[(b * N + m) * H + (c - DIN)];
    g_Xh[idx] = __float2half(v);
}

// ---------------- K5: Wn = E @ W_pool via MMA ----------------
#define EPAD 24
#define WPADW 136
__global__ void __launch_bounds__(256) k_wn(const float* __restrict__ Wz, const float* __restrict__ Wr,
                                            const float* __restrict__ Wu) {
    int g = blockIdx.z;
    const float* W = (g == 0) ? Wz : (g == 1) ? Wr : Wu;
    int ioBase = blockIdx.x * 128;
    int nBase = blockIdx.y * 64;
    __shared__ __half Eh[64 * EPAD];
    __shared__ __half Wsh[16 * WPADW];
    int t = threadIdx.x, lane = t & 31, wid = t >> 5;

    for (int idx = t; idx < 64 * 16; idx += 256) {
        int r = idx >> 4, d = idx & 15;
        Eh[r * EPAD + d] = __float2half(g_e[g][nBase + r][d]);
    }
    for (int idx = t * 4; idx < 16 * 128; idx += 1024) {
        int d = idx >> 7, c = idx & 127;
        const float4 wv = *(const float4*)&W[(size_t)d * (KI * O) + ioBase + c];
        __half* dst = &Wsh[d * WPADW + c];
        dst[0] = __float2half(wv.x); dst[1] = __float2half(wv.y);
        dst[2] = __float2half(wv.z); dst[3] = __float2half(wv.w);
    }
    __syncthreads();

    int warp_m = wid & 1, warp_n = wid >> 1;
    uint32_t ue = smem_u32(Eh), uw = smem_u32(Wsh);
    uint32_t fa[2][4], fb[2][4];
    #pragma unroll
    for (int mt = 0; mt < 2; mt++) {
        uint32_t a = ue + (uint32_t)(((warp_m * 32 + mt * 16 + (lane & 15)) * EPAD + ((lane >> 4) << 3)) * 2);
        LDM_X4(fa[mt], a);
    }
    #pragma unroll
    for (int p = 0; p < 2; p++) {
        uint32_t bptr = uw + (uint32_t)(((lane & 15) * WPADW + warp_n * 32 + p * 16 + ((lane >> 4) << 3)) * 2);
        LDM_X4_T(fb[p], bptr);
    }
    float acc[2][4][4];
    #pragma unroll
    for (int i = 0; i < 2; i++)
        #pragma unroll
        for (int j = 0; j < 4; j++)
            #pragma unroll
            for (int q = 0; q < 4; q++) acc[i][j][q] = 0.f;
    #pragma unroll
    for (int mt = 0; mt < 2; mt++)
        #pragma unroll
        for (int p = 0; p < 2; p++) {
            MMA_F16(acc[mt][2 * p],     fa[mt], &fb[p][0]);
            MMA_F16(acc[mt][2 * p + 1], fa[mt], &fb[p][2]);
        }

    #pragma unroll
    for (int mt = 0; mt < 2; mt++) {
        int n = nBase + warp_m * 32 + mt * 16 + (lane >> 2);
        #pragma unroll
        for (int nt = 0; nt < 4; nt++) {
            int io = ioBase + warp_n * 32 + nt * 8 + (lane & 3) * 2;
            *(__half2*)&g_Wnh[g][(size_t)n * (KI * O) + io] = __floats2half2_rn(acc[mt][nt][0], acc[mt][nt][1]);
            *(__half2*)&g_Wnh[g][(size_t)(n + 8) * (KI * O) + io] = __floats2half2_rn(acc[mt][nt][2], acc[mt][nt][3]);
        }
    }
}

// ---------------- K6: big GEMM — K-chunk 32, 4-stage cp.async, race-free ordering ----------------
#define APAD 40
#define BPAD 136
#define STG_A (128 * APAD)
#define STG_B (32 * BPAD)
#define STG   (STG_A + STG_B)     // 9472 halves = 18944 B/stage
#define NCH   (N / 32)
#define NSTG  4
#define GEMM_SMEM (NSTG * STG * 2) // 75776 B

__global__ void __launch_bounds__(256) k_mmagemm(int gate0, int useXc) {
    extern __shared__ __half gsm[];
    int t = threadIdx.x, lane = t & 31, wid = t >> 5;

    const __half* Aptr;
    __half* Yout;
    if (gate0 == 2) {
        Aptr = g_same[1] ? g_Af[0] : g_Af[2];
        Yout = g_Yh[2];
    } else {
        int gate = blockIdx.z;
        if (gate == 1 && g_same[0]) return;
        Aptr = g_Af[gate];
        Yout = g_Yh[gate];
    }
    const __half* Bptr = useXc ? g_Xch : g_Xh;

    int m0 = blockIdx.y * 128, c0 = blockIdx.x * 128;
    int warp_m = wid & 3, warp_n = wid >> 2;

    float acc[2][8][4];
    #pragma unroll
    for (int i = 0; i < 2; i++)
        #pragma unroll
        for (int j = 0; j < 8; j++)
            #pragma unroll
            for (int q = 0; q < 4; q++) acc[i][j][q] = 0.f;

    int arow = t >> 1, aseg = t & 1;
    const __half* gA = Aptr + (size_t)(m0 + arow) * N + aseg * 16;
    uint32_t sAoff = (uint32_t)(arow * APAD + aseg * 16) * 2;
    int brow = t >> 3, bseg = t & 7;
    const __half* gB = Bptr + c0 + bseg * 16;
    uint32_t sBoff = (uint32_t)(brow * BPAD + bseg * 16) * 2;

    uint32_t base = smem_u32(gsm);

    uint32_t aoff[2], boff[4];
    #pragma unroll
    for (int mt = 0; mt < 2; mt++)
        aoff[mt] = (uint32_t)(((warp_m * 32 + mt * 16 + (lane & 15)) * APAD + ((lane >> 4) << 3)) * 2);
    #pragma unroll
    for (int p = 0; p < 4; p++)
        boff[p] = (uint32_t)(((lane & 15) * BPAD + warp_n * 64 + p * 16 + ((lane >> 4) << 3)) * 2);

    #define ISSUE(kc, s) do { \
        const __half* pa = gA + (size_t)(kc) * 32; \
        const __half* pb = gB + (size_t)((kc) * 32 + brow) * BC; \
        uint32_t da = base + (s) * (STG * 2) + sAoff; \
        uint32_t db = base + (s) * (STG * 2) + STG_A * 2 + sBoff; \
        CP_ASYNC16(da, pa); CP_ASYNC16(da + 16, pa + 8); \
        CP_ASYNC16(db, pb); CP_ASYNC16(db + 16, pb + 8); \
        CP_COMMIT(); \
    } while (0)

    ISSUE(0, 0);
    ISSUE(1, 1);
    ISSUE(2, 2);

    for (int kc = 0; kc < NCH; kc++) {
        int st = kc & (NSTG - 1);
        if (kc >= NCH - 3) { CP_WAIT0(); } else { CP_WAIT2(); }
        __syncthreads();
        if (kc + 3 < NCH) ISSUE(kc + 3, (kc + 3) & (NSTG - 1));

        uint32_t ua = base + st * (STG * 2);
        uint32_t ub = ua + STG_A * 2;
        #pragma unroll
        for (int ks = 0; ks < 2; ks++) {
            uint32_t fa[2][4], fb[4][4];
            #pragma unroll
            for (int mt = 0; mt < 2; mt++) LDM_X4(fa[mt], ua + aoff[mt] + ks * 32);
            #pragma unroll
            for (int p = 0; p < 4; p++) LDM_X4_T(fb[p], ub + boff[p] + ks * 16 * BPAD * 2);
            #pragma unroll
            for (int mt = 0; mt < 2; mt++) {
                #pragma unroll
                for (int p = 0; p < 4; p++) {
                    MMA_F16(acc[mt][2 * p],     fa[mt], &fb[p][0]);
                    MMA_F16(acc[mt][2 * p + 1], fa[mt], &fb[p][2]);
                }
            }
        }
    }
    #undef ISSUE

    #pragma unroll
    for (int mt = 0; mt < 2; mt++) {
        int r = m0 + warp_m * 32 + mt * 16 + (lane >> 2);
        #pragma unroll
        for (int nt = 0; nt < 8; nt++) {
            int cc = c0 + warp_n * 64 + nt * 8 + (lane & 3) * 2;
            *(__half2*)&Yout[(size_t)r * BC + cc] = __floats2half2_rn(acc[mt][nt][0], acc[mt][nt][1]);
            *(__half2*)&Yout[(size_t)(r + 8) * BC + cc] = __floats2half2_rn(acc[mt][nt][2], acc[mt][nt][3]);
        }
    }
}

// ---------------- shared helper: per-node gate mini-GEMM via MMA ----------------
#define XPAD 152
#define WPAD 72

__device__ __forceinline__ void gate_mma(__half* Xall, __half* Wh,
                                         const __half* __restrict__ xsrc,
                                         const __half* __restrict__ ysrc,
                                         const __half* __restrict__ wsrc,
                                         int t, int lane, int wid,
                                         float acc[2][2][4]) {
    for (int cid = t; cid < (KI * O) / 8; cid += 256) {
        int r = cid >> 3, c8 = (cid & 7) * 8;
        *(uint4*)&Wh[r * WPAD + c8] = *(const uint4*)&wsrc[r * O + c8];
    }
    for (int cid = t; cid < 12 * 8; cid += 256) {
        int r = KI + (cid >> 3), c8 = (cid & 7) * 8;
        *(uint4*)&Wh[r * WPAD + c8] = make_uint4(0, 0, 0, 0);
    }
    for (int idx = t; idx < BC; idx += 256) {
        int b = idx / C, c = idx - b * C;
        Xall[b * XPAD + c] = xsrc[idx];
        Xall[b * XPAD + C + c] = ysrc[idx];
    }
    for (int idx = t; idx < 64 * 12; idx += 256) {
        int b = idx / 12, c = KI + idx % 12;
        Xall[b * XPAD + c] = __ushort_as_half((unsigned short)0);
    }
    __syncthreads();

    int warp_m = wid & 1, warp_n = wid >> 1;
    uint32_t ax = smem_u32(Xall), wx = smem_u32(Wh);
    uint32_t aoff[2];
    #pragma unroll
    for (int mt = 0; mt < 2; mt++)
        aoff[mt] = (uint32_t)(((warp_m * 32 + mt * 16 + (lane & 15)) * XPAD + ((lane >> 4) << 3)) * 2);
    uint32_t boff = (uint32_t)(((lane & 15) * WPAD + warp_n * 16 + ((lane >> 4) << 3)) * 2);

    #pragma unroll
    for (int ks = 0; ks < KIP / 16; ks++) {
        uint32_t fa[2][4], fb[4];
        LDM_X4(fa[0], ax + aoff[0] + ks * 32);
        LDM_X4(fa[1], ax + aoff[1] + ks * 32);
        LDM_X4_T(fb, wx + boff + (uint32_t)(ks * 16 * WPAD * 2));
        #pragma unroll
        for (int mt = 0; mt < 2; mt++) {
            MMA_F16(acc[mt][0], fa[mt], &fb[0]);
            MMA_F16(acc[mt][1], fa[mt], &fb[2]);
        }
    }
}

// ---------------- K7a: z gate (critical path: produces Xc) ----------------
__global__ void __launch_bounds__(256) k_gate_z(const float* __restrict__ state) {
    __shared__ __half Xall[64 * XPAD];
    __shared__ __half Wh[KIP * WPAD];
    int n = blockIdx.x;
    int t = threadIdx.x, lane = t & 31, wid = t >> 5;

    const __half* xsrc = g_Xh + (size_t)n * BC;
    const __half* ysrc = g_Yh[0] + (size_t)n * BC;
    const __half* wsrc = g_Wnh[0] + (size_t)n * (KI * O);

    float acc[2][2][4];
    #pragma unroll
    for (int i = 0; i < 2; i++)
        #pragma unroll
        for (int j = 0; j < 2; j++)
            #pragma unroll
            for (int q = 0; q < 4; q++) acc[i][j][q] = 0.f;

    gate_mma(Xall, Wh, xsrc, ysrc, wsrc, t, lane, wid, acc);

    int warp_m = wid & 1, warp_n = wid >> 1;
    #pragma unroll
    for (int mt = 0; mt < 2; mt++) {
        int b = warp_m * 32 + mt * 16 + (lane >> 2);
        #pragma unroll
        for (int nt = 0; nt < 2; nt++) {
            int o = warp_n * 16 + nt * 8 + (lane & 3) * 2;
            #pragma unroll
            for (int hf = 0; hf < 2; hf++) {
                int bb = b + hf * 8;
                float2 bi = *(const float2*)&g_bias[0][n][o];
                float s0 = sigmoidf_(acc[mt][nt][2 * hf + 0] + bi.x);
                float s1 = sigmoidf_(acc[mt][nt][2 * hf + 1] + bi.y);
                float2 st = *(const float2*)&state[((size_t)bb * N + n) * H + o];
                *(__half2*)&g_Xch[(size_t)n * BC + bb * C + DIN + o] =
                    __floats2half2_rn(s0 * st.x, s1 * st.y);
            }
        }
    }
    if (t < B * DIN) {
        int b = t >> 1, c = t & 1;
        g_Xch[(size_t)n * BC + b * C + c] = xsrc[b * C + c];
    }
}

// ---------------- K7b: r gate (off critical path: overlapped with GEMM-u) ----------------
__global__ void __launch_bounds__(256) k_gate_r() {
    __shared__ __half Xall[64 * XPAD];
    __shared__ __half Wh[KIP * WPAD];
    int n = blockIdx.x;
    int t = threadIdx.x, lane = t & 31, wid = t >> 5;

    const __half* xsrc = g_Xh + (size_t)n * BC;
    const __half* ysrc = g_same[0] ? (g_Yh[0] + (size_t)n * BC)
                                   : (g_Yh[1] + (size_t)n * BC);
    const __half* wsrc = g_Wnh[1] + (size_t)n * (KI * O);

    float acc[2][2][4];
    #pragma unroll
    for (int i = 0; i < 2; i++)
        #pragma unroll
        for (int j = 0; j < 2; j++)
            #pragma unroll
            for (int q = 0; q < 4; q++) acc[i][j][q] = 0.f;

    gate_mma(Xall, Wh, xsrc, ysrc, wsrc, t, lane, wid, acc);

    int warp_m = wid & 1, warp_n = wid >> 1;
    #pragma unroll
    for (int mt = 0; mt < 2; mt++) {
        int b = warp_m * 32 + mt * 16 + (lane >> 2);
        #pragma unroll
        for (int nt = 0; nt < 2; nt++) {
            int o = warp_n * 16 + nt * 8 + (lane & 3) * 2;
            #pragma unroll
            for (int hf = 0; hf < 2; hf++) {
                int bb = b + hf * 8;
                float2 bi = *(const float2*)&g_bias[1][n][o];
                float s0 = sigmoidf_(acc[mt][nt][2 * hf + 0] + bi.x);
                float s1 = sigmoidf_(acc[mt][nt][2 * hf + 1] + bi.y);
                *(float2*)&g_r[((size_t)n * B + bb) * O + o] = make_float2(s0, s1);
            }
        }
    }
}

// ---------------- K8: final u gate + GRU combine ----------------
__global__ void __launch_bounds__(256) k_final(const float* __restrict__ state, float* __restrict__ out) {
    __shared__ __half Xall[64 * XPAD];
    __shared__ __half Wh[KIP * WPAD];
    int n = blockIdx.x;
    int t = threadIdx.x, lane = t & 31, wid = t >> 5;

    const __half* xsrc = g_Xch + (size_t)n * BC;
    const __half* ysrc = g_Yh[2] + (size_t)n * BC;
    const __half* wsrc = g_Wnh[2] + (size_t)n * (KI * O);

    float acc[2][2][4];
    #pragma unroll
    for (int i = 0; i < 2; i++)
        #pragma unroll
        for (int j = 0; j < 2; j++)
            #pragma unroll
            for (int q = 0; q < 4; q++) acc[i][j][q] = 0.f;

    gate_mma(Xall, Wh, xsrc, ysrc, wsrc, t, lane, wid, acc);

    int warp_m = wid & 1, warp_n = wid >> 1;
    #pragma unroll
    for (int mt = 0; mt < 2; mt++) {
        int b = warp_m * 32 + mt * 16 + (lane >> 2);
        #pragma unroll
        for (int nt = 0; nt < 2; nt++) {
            int o = warp_n * 16 + nt * 8 + (lane & 3) * 2;
            #pragma unroll
            for (int hf = 0; hf < 2; hf++) {
                int bb = b + hf * 8;
                float2 bi = *(const float2*)&g_bias[2][n][o];
                float hc0 = tanhf(acc[mt][nt][2 * hf + 0] + bi.x);
                float hc1 = tanhf(acc[mt][nt][2 * hf + 1] + bi.y);
                float2 rr = *(const float2*)&g_r[((size_t)n * B + bb) * O + o];
                float2 st = *(const float2*)&state[((size_t)bb * N + n) * H + o];
                *(float2*)&out[((size_t)bb * N + n) * O + o] =
                    make_float2(rr.x * st.x + (1.0f - rr.x) * hc0,
                                rr.y * st.y + (1.0f - rr.y) * hc1);
            }
        }
    }
}

// ---------------- launch (two streams, event-linked, graph-capturable) ----------------
extern "C" void kernel_launch(void* const* d_in, const int* in_sizes, int n_in,
                              void* d_out, int out_size) {
    const float* x     = (const float*)d_in[0];
    const float* state = (const float*)d_in[1];
    const float* ne    = (const float*)d_in[2];
    const float* te    = (const float*)d_in[3];
    const float* W_z   = (const float*)d_in[4];
    const float* b_z   = (const float*)d_in[5];
    const float* gam_z = (const float*)d_in[6];
    const float* bet_z = (const float*)d_in[7];
    const float* W_r   = (const float*)d_in[8];
    const float* b_r   = (const float*)d_in[9];
    const float* gam_r = (const float*)d_in[10];
    const float* bet_r = (const float*)d_in[11];
    const float* W_u   = (const float*)d_in[12];
    const float* b_u   = (const float*)d_in[13];
    const float* gam_u = (const float*)d_in[14];
    const float* bet_u = (const float*)d_in[15];
    float* out = (float*)d_out;

    static cudaStream_t s2 = nullptr;
    static cudaEvent_t eEmb = nullptr, eBXh = nullptr, eW = nullptr, eGz = nullptr, eR = nullptr;
    if (s2 == nullptr) {
        cudaStreamCreateWithFlags(&s2, cudaStreamNonBlocking);
        cudaEventCreateWithFlags(&eEmb, cudaEventDisableTiming);
        cudaEventCreateWithFlags(&eBXh, cudaEventDisableTiming);
        cudaEventCreateWithFlags(&eW, cudaEventDisableTiming);
        cudaEventCreateWithFlags(&eGz, cudaEventDisableTiming);
        cudaEventCreateWithFlags(&eR, cudaEventDisableTiming);
        cudaFuncSetAttribute(k_mmagemm, cudaFuncAttributeMaxDynamicSharedMemorySize, GEMM_SMEM);
    }

    // main stream (0): embed -> adj -> GEMM_z -> gate_z -> GEMM_u -> final
    // side stream s2:  buildXh -> wn -> bias -> gate_r (gate_r overlaps GEMM_u)
    k_embed<<<N, 32>>>(ne, te, gam_z, bet_z, gam_r, bet_r, gam_u, bet_u);       // #1
    cudaEventRecord(eEmb, 0);
    cudaStreamWaitEvent(s2, eEmb, 0);

    k_adj<<<dim3(N / 4, 3), 256>>>();                                           // #2 (stream 0)
    k_buildXh<<<(N * BC + 255) / 256, 256, 0, s2>>>(x, state);                  // #3 (s2)
    cudaEventRecord(eBXh, s2);

    cudaStreamWaitEvent(0, eBXh, 0);
    k_mmagemm<<<dim3(BC / 128, N / 128, 2), 256, GEMM_SMEM>>>(0, 0);            // #4 <- profiled
    cudaEventRecord(eGz, 0);

    k_wn<<<dim3(66, 32, 3), 256, 0, s2>>>(W_z, W_r, W_u);                       // #5 (s2)
    k_bias<<<(3 * N * O + 255) / 256, 256, 0, s2>>>(b_z, b_r, b_u);             // #6 (s2)
    cudaEventRecord(eW, s2);

    // main: z gate (needs wn/bias + Y_z)
    cudaStreamWaitEvent(0, eW, 0);
    k_gate_z<<<N, 256>>>(state);                                                // #7 (stream 0)

    // s2: r gate (needs Y_z from GEMM-z) — overlaps with GEMM-u below
    cudaStreamWaitEvent(s2, eGz, 0);
    k_gate_r<<<N, 256, 0, s2>>>();                                              // (s2)
    cudaEventRecord(eR, s2);

    k_mmagemm<<<dim3(BC / 128, N / 128, 1), 256, GEMM_SMEM>>>(2, 1);            // #8 (stream 0)

    cudaStreamWaitEvent(0, eR, 0);
    k_final<<<N, 256>>>(state, out);                                            // #9
}